// round 1
// baseline (speedup 1.0000x reference)
#include <cuda_runtime.h>

// ---------------------------------------------------------------------------
// TalkingHeadAttn  (B=16, N=576, C=768, H=12, HD=64)
// Staged fp32 baseline:
//   K1: qkv = x @ Wqkv^T  -> scatter into q (pre-scaled), k, v  [B,H,N,HD]
//   K2: S[b,h] = q[b,h] @ k[b,h]^T                              [B,H,N,N]
//   K3: fused pre-mix(Wl,bl) + softmax(n) + post-mix(Ww,bw), in-place on S
//   K4: Ohead[b,h] = S[b,h] @ v[b,h]  -> (B,N,C) layout
//   K5: out = Ohead @ Wproj^T + bproj
// ---------------------------------------------------------------------------

#define Bb 16
#define Nn 576
#define Cc 768
#define Hh 12
#define HDm 64
#define BN (Bb * Nn)        // 9216
#define C3 (3 * Cc)         // 2304
#define QK_SCALE 0.125f     // 1/sqrt(64)

// scratch (static device globals: allocation-free contract)
__device__ float g_q[(size_t)Bb * Hh * Nn * HDm];
__device__ float g_k[(size_t)Bb * Hh * Nn * HDm];
__device__ float g_v[(size_t)Bb * Hh * Nn * HDm];
__device__ float g_s[(size_t)Bb * Hh * Nn * Nn];   // 255 MB, reused for P2
__device__ float g_oh[(size_t)BN * Cc];

// ---------------------------------------------------------------------------
// K1: C[m,l] = sum_k X[m,k] * Wqkv[l,k], M=9216, L=2304, K=768
// 128x128 tile, BK=8, 256 threads, 8x8 per-thread microtile.
// Epilogue scatters into g_q/g_k/g_v.
// ---------------------------------------------------------------------------
__global__ void __launch_bounds__(256) k_qkv(const float* __restrict__ X,
                                             const float* __restrict__ W) {
    __shared__ float As[8][128];
    __shared__ float Bs[8][128];
    const int bm = blockIdx.y * 128;
    const int bl = blockIdx.x * 128;
    const int t  = threadIdx.x;
    const int lr = t >> 1;          // 0..127
    const int lk = (t & 1) * 4;     // 0 or 4
    const int tr = (t >> 4) * 8;    // 0..120
    const int tc = (t & 15) * 8;    // 0..120

    float acc[8][8];
#pragma unroll
    for (int i = 0; i < 8; i++)
#pragma unroll
        for (int j = 0; j < 8; j++) acc[i][j] = 0.f;

    for (int k0 = 0; k0 < Cc; k0 += 8) {
        float4 av = *reinterpret_cast<const float4*>(X + (size_t)(bm + lr) * Cc + k0 + lk);
        float4 bv = *reinterpret_cast<const float4*>(W + (size_t)(bl + lr) * Cc + k0 + lk);
        __syncthreads();
        As[lk + 0][lr] = av.x; As[lk + 1][lr] = av.y; As[lk + 2][lr] = av.z; As[lk + 3][lr] = av.w;
        Bs[lk + 0][lr] = bv.x; Bs[lk + 1][lr] = bv.y; Bs[lk + 2][lr] = bv.z; Bs[lk + 3][lr] = bv.w;
        __syncthreads();
#pragma unroll
        for (int kk = 0; kk < 8; kk++) {
            float a[8], b[8];
#pragma unroll
            for (int i = 0; i < 8; i++) a[i] = As[kk][tr + i];
#pragma unroll
            for (int j = 0; j < 8; j++) b[j] = Bs[kk][tc + j];
#pragma unroll
            for (int i = 0; i < 8; i++)
#pragma unroll
                for (int j = 0; j < 8; j++) acc[i][j] = fmaf(a[i], b[j], acc[i][j]);
        }
    }
    // scatter epilogue: l -> (s, h, d); m -> (b, n)
#pragma unroll
    for (int i = 0; i < 8; i++) {
        const int m  = bm + tr + i;
        const int bi = m / Nn;
        const int ni = m - bi * Nn;
#pragma unroll
        for (int j = 0; j < 8; j++) {
            const int l   = bl + tc + j;
            const int s   = l / Cc;
            const int rem = l - s * Cc;
            const int h   = rem >> 6;
            const int d   = rem & 63;
            const size_t dst = ((size_t)((bi * Hh + h) * Nn + ni)) * HDm + d;
            const float v = acc[i][j];
            if (s == 0)      g_q[dst] = v * QK_SCALE;
            else if (s == 1) g_k[dst] = v;
            else             g_v[dst] = v;
        }
    }
}

// ---------------------------------------------------------------------------
// K2: per (b,h): S[m,n] = sum_d q[m,d]*k[n,d]. 64x64 tile, BK=16, 256 thr, 4x4.
// ---------------------------------------------------------------------------
__global__ void __launch_bounds__(256) k_scores() {
    const int bh = blockIdx.z;
    const float* Q = g_q + (size_t)bh * Nn * HDm;
    const float* K = g_k + (size_t)bh * Nn * HDm;
    float* S = g_s + (size_t)bh * Nn * Nn;

    __shared__ __align__(16) float Qs[16][64];
    __shared__ __align__(16) float Ks[16][64];
    const int bm = blockIdx.y * 64;
    const int bn = blockIdx.x * 64;
    const int t  = threadIdx.x;
    const int lr = t >> 2;          // 0..63
    const int lk = (t & 3) * 4;     // 0,4,8,12
    const int tr = (t >> 4) * 4;
    const int tc = (t & 15) * 4;

    float acc[4][4];
#pragma unroll
    for (int i = 0; i < 4; i++)
#pragma unroll
        for (int j = 0; j < 4; j++) acc[i][j] = 0.f;

    for (int k0 = 0; k0 < HDm; k0 += 16) {
        float4 qv = *reinterpret_cast<const float4*>(Q + (size_t)(bm + lr) * HDm + k0 + lk);
        float4 kv = *reinterpret_cast<const float4*>(K + (size_t)(bn + lr) * HDm + k0 + lk);
        __syncthreads();
        Qs[lk + 0][lr] = qv.x; Qs[lk + 1][lr] = qv.y; Qs[lk + 2][lr] = qv.z; Qs[lk + 3][lr] = qv.w;
        Ks[lk + 0][lr] = kv.x; Ks[lk + 1][lr] = kv.y; Ks[lk + 2][lr] = kv.z; Ks[lk + 3][lr] = kv.w;
        __syncthreads();
#pragma unroll
        for (int kk = 0; kk < 16; kk++) {
            float a[4], b[4];
#pragma unroll
            for (int i = 0; i < 4; i++) a[i] = Qs[kk][tr + i];
#pragma unroll
            for (int j = 0; j < 4; j++) b[j] = Ks[kk][tc + j];
#pragma unroll
            for (int i = 0; i < 4; i++)
#pragma unroll
                for (int j = 0; j < 4; j++) acc[i][j] = fmaf(a[i], b[j], acc[i][j]);
        }
    }
#pragma unroll
    for (int i = 0; i < 4; i++)
#pragma unroll
        for (int j = 0; j < 4; j++)
            S[(size_t)(bm + tr + i) * Nn + bn + tc + j] = acc[i][j];
}

// ---------------------------------------------------------------------------
// K3: fused talking-heads: per (b,m) CTA, 576 threads (one per n).
//   a[g,n] = sum_h Wl[g,h]*S[h,n] + bl[g]; softmax over n per g;
//   P2[g,n] = sum_h Ww[g,h]*p[h,n] + bw[g]; write in place.
// ---------------------------------------------------------------------------
__global__ void __launch_bounds__(576) k_mix_softmax(const float* __restrict__ Wl,
                                                     const float* __restrict__ bl,
                                                     const float* __restrict__ Ww,
                                                     const float* __restrict__ bw) {
    const int bm = blockIdx.x;          // 0..9215
    const int b  = bm / Nn;
    const int m  = bm - b * Nn;
    const int n  = threadIdx.x;         // 0..575
    const int lane = threadIdx.x & 31;
    const int wp   = threadIdx.x >> 5;  // 0..17

    __shared__ float sWl[144], sWw[144], sbl[12], sbw[12];
    __shared__ float red[12][20];
    __shared__ float rowstat[12];

    if (threadIdx.x < 144) { sWl[threadIdx.x] = Wl[threadIdx.x]; sWw[threadIdx.x] = Ww[threadIdx.x]; }
    if (threadIdx.x < 12)  { sbl[threadIdx.x] = bl[threadIdx.x]; sbw[threadIdx.x] = bw[threadIdx.x]; }
    __syncthreads();

    const size_t base = ((size_t)(b * Hh) * Nn + m) * Nn + n;   // h stride = Nn*Nn
    const size_t hstr = (size_t)Nn * Nn;

    float s[12];
#pragma unroll
    for (int h = 0; h < 12; h++) s[h] = g_s[base + (size_t)h * hstr];

    float a[12];
#pragma unroll
    for (int g = 0; g < 12; g++) {
        float acc = sbl[g];
#pragma unroll
        for (int h = 0; h < 12; h++) acc = fmaf(sWl[g * 12 + h], s[h], acc);
        a[g] = acc;
    }

    // per-g max over n
#pragma unroll
    for (int g = 0; g < 12; g++) {
        float v = a[g];
#pragma unroll
        for (int o = 16; o > 0; o >>= 1) v = fmaxf(v, __shfl_xor_sync(0xffffffffu, v, o));
        if (lane == 0) red[g][wp] = v;
    }
    __syncthreads();
    if (threadIdx.x < 12) {
        float v = red[threadIdx.x][0];
        for (int w2 = 1; w2 < 18; w2++) v = fmaxf(v, red[threadIdx.x][w2]);
        rowstat[threadIdx.x] = v;
    }
    __syncthreads();

    float p[12];
#pragma unroll
    for (int g = 0; g < 12; g++) p[g] = __expf(a[g] - rowstat[g]);
    __syncthreads();   // rowstat reads done before reuse of red/rowstat

    // per-g sum over n
#pragma unroll
    for (int g = 0; g < 12; g++) {
        float v = p[g];
#pragma unroll
        for (int o = 16; o > 0; o >>= 1) v += __shfl_xor_sync(0xffffffffu, v, o);
        if (lane == 0) red[g][wp] = v;
    }
    __syncthreads();
    if (threadIdx.x < 12) {
        float v = 0.f;
        for (int w2 = 0; w2 < 18; w2++) v += red[threadIdx.x][w2];
        rowstat[threadIdx.x] = 1.0f / v;
    }
    __syncthreads();

#pragma unroll
    for (int g = 0; g < 12; g++) p[g] *= rowstat[g];

    // post-softmax mix + in-place write (thread n only touches column n: safe)
#pragma unroll
    for (int g = 0; g < 12; g++) {
        float acc = sbw[g];
#pragma unroll
        for (int h = 0; h < 12; h++) acc = fmaf(sWw[g * 12 + h], p[h], acc);
        g_s[base + (size_t)g * hstr] = acc;
    }
}

// ---------------------------------------------------------------------------
// K4: per (b,h): O[m,d] = sum_n P[m,n]*V[n,d]. 64(M)x64(D) tile, BK=16.
// Output into g_oh laid out (B,N,C) with c = h*64+d.
// ---------------------------------------------------------------------------
__global__ void __launch_bounds__(256) k_pv() {
    const int bh = blockIdx.z;
    const int b  = bh / Hh;
    const int h  = bh - b * Hh;
    const float* P = g_s + (size_t)bh * Nn * Nn;
    const float* V = g_v + (size_t)bh * Nn * HDm;

    __shared__ __align__(16) float Ps[16][64];
    __shared__ __align__(16) float Vs[16][64];
    const int bm = blockIdx.y * 64;
    const int t  = threadIdx.x;
    const int pr = t >> 2;          // 0..63  (P row)
    const int pk = (t & 3) * 4;     // 0..12  (P k-col)
    const int vr = t >> 4;          // 0..15  (V row)
    const int vc = (t & 15) * 4;    // 0..60  (V col)
    const int tr = (t >> 4) * 4;
    const int tc = (t & 15) * 4;

    float acc[4][4];
#pragma unroll
    for (int i = 0; i < 4; i++)
#pragma unroll
        for (int j = 0; j < 4; j++) acc[i][j] = 0.f;

    for (int k0 = 0; k0 < Nn; k0 += 16) {
        float4 pv = *reinterpret_cast<const float4*>(P + (size_t)(bm + pr) * Nn + k0 + pk);
        float4 vv = *reinterpret_cast<const float4*>(V + (size_t)(k0 + vr) * HDm + vc);
        __syncthreads();
        Ps[pk + 0][pr] = pv.x; Ps[pk + 1][pr] = pv.y; Ps[pk + 2][pr] = pv.z; Ps[pk + 3][pr] = pv.w;
        *reinterpret_cast<float4*>(&Vs[vr][vc]) = vv;
        __syncthreads();
#pragma unroll
        for (int kk = 0; kk < 16; kk++) {
            float a[4], bx[4];
#pragma unroll
            for (int i = 0; i < 4; i++) a[i]  = Ps[kk][tr + i];
#pragma unroll
            for (int j = 0; j < 4; j++) bx[j] = Vs[kk][tc + j];
#pragma unroll
            for (int i = 0; i < 4; i++)
#pragma unroll
                for (int j = 0; j < 4; j++) acc[i][j] = fmaf(a[i], bx[j], acc[i][j]);
        }
    }
#pragma unroll
    for (int i = 0; i < 4; i++) {
        const int m = bm + tr + i;
#pragma unroll
        for (int j = 0; j < 4; j++) {
            const int d = tc + j;
            g_oh[(size_t)(b * Nn + m) * Cc + h * HDm + d] = acc[i][j];
        }
    }
}

// ---------------------------------------------------------------------------
// K5: out[m,l] = sum_k g_oh[m,k]*Wproj[l,k] + bproj[l]. M=9216, L=768, K=768.
// Same scheme as K1.
// ---------------------------------------------------------------------------
__global__ void __launch_bounds__(256) k_proj(const float* __restrict__ W,
                                              const float* __restrict__ bias,
                                              float* __restrict__ out) {
    __shared__ float As[8][128];
    __shared__ float Bs[8][128];
    const int bm = blockIdx.y * 128;
    const int bl = blockIdx.x * 128;
    const int t  = threadIdx.x;
    const int lr = t >> 1;
    const int lk = (t & 1) * 4;
    const int tr = (t >> 4) * 8;
    const int tc = (t & 15) * 8;

    float acc[8][8];
#pragma unroll
    for (int i = 0; i < 8; i++)
#pragma unroll
        for (int j = 0; j < 8; j++) acc[i][j] = 0.f;

    for (int k0 = 0; k0 < Cc; k0 += 8) {
        float4 av = *reinterpret_cast<const float4*>(g_oh + (size_t)(bm + lr) * Cc + k0 + lk);
        float4 bv = *reinterpret_cast<const float4*>(W + (size_t)(bl + lr) * Cc + k0 + lk);
        __syncthreads();
        As[lk + 0][lr] = av.x; As[lk + 1][lr] = av.y; As[lk + 2][lr] = av.z; As[lk + 3][lr] = av.w;
        Bs[lk + 0][lr] = bv.x; Bs[lk + 1][lr] = bv.y; Bs[lk + 2][lr] = bv.z; Bs[lk + 3][lr] = bv.w;
        __syncthreads();
#pragma unroll
        for (int kk = 0; kk < 8; kk++) {
            float a[8], b[8];
#pragma unroll
            for (int i = 0; i < 8; i++) a[i] = As[kk][tr + i];
#pragma unroll
            for (int j = 0; j < 8; j++) b[j] = Bs[kk][tc + j];
#pragma unroll
            for (int i = 0; i < 8; i++)
#pragma unroll
                for (int j = 0; j < 8; j++) acc[i][j] = fmaf(a[i], b[j], acc[i][j]);
        }
    }
#pragma unroll
    for (int i = 0; i < 8; i++) {
        const int m = bm + tr + i;
#pragma unroll
        for (int j = 0; j < 8; j++) {
            const int l = bl + tc + j;
            out[(size_t)m * Cc + l] = acc[i][j] + bias[l];
        }
    }
}

// ---------------------------------------------------------------------------
extern "C" void kernel_launch(void* const* d_in, const int* in_sizes, int n_in,
                              void* d_out, int out_size) {
    const float* x     = (const float*)d_in[0];
    const float* Wqkv  = (const float*)d_in[1];
    const float* Wl    = (const float*)d_in[2];
    const float* bl    = (const float*)d_in[3];
    const float* Ww    = (const float*)d_in[4];
    const float* bw    = (const float*)d_in[5];
    const float* Wproj = (const float*)d_in[6];
    const float* bproj = (const float*)d_in[7];
    float* out = (float*)d_out;

    k_qkv<<<dim3(C3 / 128, BN / 128), 256>>>(x, Wqkv);                 // 18 x 72
    k_scores<<<dim3(Nn / 64, Nn / 64, Bb * Hh), 256>>>();              // 9 x 9 x 192
    k_mix_softmax<<<BN, 576>>>(Wl, bl, Ww, bw);                        // 9216 CTAs
    k_pv<<<dim3(1, Nn / 64, Bb * Hh), 256>>>();                        // 1 x 9 x 192
    k_proj<<<dim3(Cc / 128, BN / 128), 256>>>(Wproj, bproj, out);      // 6 x 72
}

// round 2
// speedup vs baseline: 1.4385x; 1.4385x over previous
#include <cuda_runtime.h>
#include <cuda_bf16.h>
#include <cstdint>

// ---------------------------------------------------------------------------
// TalkingHeadAttn  (B=16, N=576, C=768, H=12, HD=64)
// R1: qkv & proj GEMMs on tensor cores (mma.sync m16n8k16 bf16, 2-term split,
//     3-MMA product => ~fp32 accuracy). scores/softmax/pv unchanged fp32 SIMT.
// ---------------------------------------------------------------------------

#define Bb 16
#define Nn 576
#define Cc 768
#define Hh 12
#define HDm 64
#define BN (Bb * Nn)        // 9216
#define C3 (3 * Cc)         // 2304
#define QK_SCALE 0.125f

// scratch (static device globals: allocation-free contract)
__device__ float g_q[(size_t)Bb * Hh * Nn * HDm];
__device__ float g_k[(size_t)Bb * Hh * Nn * HDm];
__device__ float g_v[(size_t)Bb * Hh * Nn * HDm];
__device__ float g_s[(size_t)Bb * Hh * Nn * Nn];   // 255 MB, reused for P2

// bf16 split buffers
__device__ __nv_bfloat16 g_xhi[(size_t)BN * Cc],  g_xlo[(size_t)BN * Cc];
__device__ __nv_bfloat16 g_wqhi[(size_t)C3 * Cc], g_wqlo[(size_t)C3 * Cc];
__device__ __nv_bfloat16 g_wphi[(size_t)Cc * Cc], g_wplo[(size_t)Cc * Cc];
__device__ __nv_bfloat16 g_ohhi[(size_t)BN * Cc], g_ohlo[(size_t)BN * Cc];

// ---------------------------------------------------------------------------
// split fp32 -> (bf16 hi, bf16 lo)
// ---------------------------------------------------------------------------
__global__ void k_split(const float* __restrict__ src,
                        __nv_bfloat16* __restrict__ hi,
                        __nv_bfloat16* __restrict__ lo, int n) {
    int i = blockIdx.x * blockDim.x + threadIdx.x;
    if (i < n) {
        float x = src[i];
        __nv_bfloat16 h = __float2bfloat16_rn(x);
        float r = x - __bfloat162float(h);
        hi[i] = h;
        lo[i] = __float2bfloat16_rn(r);
    }
}

// ---------------------------------------------------------------------------
// bf16 split GEMM: C[m,l] = sum_k A[m,k] * W[l,k], K=768.
// CTA 128x128, BK=32, 256 thr = 8 warps (2x4), warp tile 64x32.
// MODE 0: qkv scatter epilogue. MODE 1: proj bias epilogue.
// ---------------------------------------------------------------------------
#define MMA_BF16(C, A, B)                                                     \
    asm volatile(                                                             \
        "mma.sync.aligned.m16n8k16.row.col.f32.bf16.bf16.f32 "                \
        "{%0,%1,%2,%3}, {%4,%5,%6,%7}, {%8,%9}, {%0,%1,%2,%3};\n"             \
        : "+f"((C)[0]), "+f"((C)[1]), "+f"((C)[2]), "+f"((C)[3])              \
        : "r"((A)[0]), "r"((A)[1]), "r"((A)[2]), "r"((A)[3]),                 \
          "r"((B)[0]), "r"((B)[1]))

template <int MODE>
__global__ void __launch_bounds__(256) k_gemm_bf16(
    const __nv_bfloat16* __restrict__ Ahi, const __nv_bfloat16* __restrict__ Alo,
    const __nv_bfloat16* __restrict__ Whi, const __nv_bfloat16* __restrict__ Wlo,
    const float* __restrict__ bias, float* __restrict__ out) {

    __shared__ __nv_bfloat16 sAh[128][40], sAl[128][40];
    __shared__ __nv_bfloat16 sBh[128][40], sBl[128][40];

    const int bm  = blockIdx.y * 128;
    const int blb = blockIdx.x * 128;
    const int t    = threadIdx.x;
    const int lane = t & 31;
    const int warp = t >> 5;
    const int gid  = lane >> 2;
    const int tig  = lane & 3;
    const int wm   = (warp >> 2) * 64;
    const int wn   = (warp & 3) * 32;

    // staging: thread t loads row srow, 16 bf16 (hi+lo) of A and of W per tile
    const int srow = t >> 1;
    const int scg  = (t & 1) * 16;

    float acc[4][4][4];
#pragma unroll
    for (int mt = 0; mt < 4; mt++)
#pragma unroll
        for (int nt = 0; nt < 4; nt++)
#pragma unroll
            for (int r = 0; r < 4; r++) acc[mt][nt][r] = 0.f;

    const size_t aBase = (size_t)(bm + srow) * Cc;
    const size_t bBase = (size_t)(blb + srow) * Cc;

    uint4 rah0, rah1, ral0, ral1, rbh0, rbh1, rbl0, rbl1;
    {
        const uint4* p;
        p = reinterpret_cast<const uint4*>(Ahi + aBase + scg); rah0 = p[0]; rah1 = p[1];
        p = reinterpret_cast<const uint4*>(Alo + aBase + scg); ral0 = p[0]; ral1 = p[1];
        p = reinterpret_cast<const uint4*>(Whi + bBase + scg); rbh0 = p[0]; rbh1 = p[1];
        p = reinterpret_cast<const uint4*>(Wlo + bBase + scg); rbl0 = p[0]; rbl1 = p[1];
    }

    for (int k0 = 0; k0 < Cc; k0 += 32) {
        __syncthreads();
        *reinterpret_cast<uint4*>(&sAh[srow][scg])     = rah0;
        *reinterpret_cast<uint4*>(&sAh[srow][scg + 8]) = rah1;
        *reinterpret_cast<uint4*>(&sAl[srow][scg])     = ral0;
        *reinterpret_cast<uint4*>(&sAl[srow][scg + 8]) = ral1;
        *reinterpret_cast<uint4*>(&sBh[srow][scg])     = rbh0;
        *reinterpret_cast<uint4*>(&sBh[srow][scg + 8]) = rbh1;
        *reinterpret_cast<uint4*>(&sBl[srow][scg])     = rbl0;
        *reinterpret_cast<uint4*>(&sBl[srow][scg + 8]) = rbl1;
        __syncthreads();

        if (k0 + 32 < Cc) {
            const int kn = k0 + 32;
            const uint4* p;
            p = reinterpret_cast<const uint4*>(Ahi + aBase + kn + scg); rah0 = p[0]; rah1 = p[1];
            p = reinterpret_cast<const uint4*>(Alo + aBase + kn + scg); ral0 = p[0]; ral1 = p[1];
            p = reinterpret_cast<const uint4*>(Whi + bBase + kn + scg); rbh0 = p[0]; rbh1 = p[1];
            p = reinterpret_cast<const uint4*>(Wlo + bBase + kn + scg); rbl0 = p[0]; rbl1 = p[1];
        }

#pragma unroll
        for (int kk = 0; kk < 32; kk += 16) {
            uint32_t ah[4][4], al[4][4];
#pragma unroll
            for (int mt = 0; mt < 4; mt++) {
                const int r0 = wm + mt * 16 + gid;
                ah[mt][0] = *reinterpret_cast<const uint32_t*>(&sAh[r0][kk + tig * 2]);
                ah[mt][1] = *reinterpret_cast<const uint32_t*>(&sAh[r0 + 8][kk + tig * 2]);
                ah[mt][2] = *reinterpret_cast<const uint32_t*>(&sAh[r0][kk + tig * 2 + 8]);
                ah[mt][3] = *reinterpret_cast<const uint32_t*>(&sAh[r0 + 8][kk + tig * 2 + 8]);
                al[mt][0] = *reinterpret_cast<const uint32_t*>(&sAl[r0][kk + tig * 2]);
                al[mt][1] = *reinterpret_cast<const uint32_t*>(&sAl[r0 + 8][kk + tig * 2]);
                al[mt][2] = *reinterpret_cast<const uint32_t*>(&sAl[r0][kk + tig * 2 + 8]);
                al[mt][3] = *reinterpret_cast<const uint32_t*>(&sAl[r0 + 8][kk + tig * 2 + 8]);
            }
            uint32_t bh[4][2], blr[4][2];
#pragma unroll
            for (int nt = 0; nt < 4; nt++) {
                const int c0 = wn + nt * 8 + gid;
                bh[nt][0]  = *reinterpret_cast<const uint32_t*>(&sBh[c0][kk + tig * 2]);
                bh[nt][1]  = *reinterpret_cast<const uint32_t*>(&sBh[c0][kk + tig * 2 + 8]);
                blr[nt][0] = *reinterpret_cast<const uint32_t*>(&sBl[c0][kk + tig * 2]);
                blr[nt][1] = *reinterpret_cast<const uint32_t*>(&sBl[c0][kk + tig * 2 + 8]);
            }
#pragma unroll
            for (int mt = 0; mt < 4; mt++)
#pragma unroll
                for (int nt = 0; nt < 4; nt++) {
                    MMA_BF16(acc[mt][nt], ah[mt], bh[nt]);
                    MMA_BF16(acc[mt][nt], ah[mt], blr[nt]);
                    MMA_BF16(acc[mt][nt], al[mt], bh[nt]);
                }
        }
    }

    // epilogue
#pragma unroll
    for (int mt = 0; mt < 4; mt++) {
#pragma unroll
        for (int nt = 0; nt < 4; nt++) {
#pragma unroll
            for (int r = 0; r < 4; r++) {
                const int m = bm + wm + mt * 16 + gid + ((r >= 2) ? 8 : 0);
                const int l = blb + wn + nt * 8 + tig * 2 + (r & 1);
                const float v = acc[mt][nt][r];
                if (MODE == 0) {
                    const int bi  = m / Nn;
                    const int ni  = m - bi * Nn;
                    const int s   = l / Cc;
                    const int rem = l - s * Cc;
                    const int h   = rem >> 6;
                    const int d   = rem & 63;
                    const size_t dst = ((size_t)((bi * Hh + h) * Nn + ni)) * HDm + d;
                    if (s == 0)      g_q[dst] = v * QK_SCALE;
                    else if (s == 1) g_k[dst] = v;
                    else             g_v[dst] = v;
                } else {
                    out[(size_t)m * Cc + l] = v + bias[l];
                }
            }
        }
    }
}

// ---------------------------------------------------------------------------
// K2: per (b,h): S[m,n] = sum_d q[m,d]*k[n,d]. (unchanged fp32 SIMT)
// ---------------------------------------------------------------------------
__global__ void __launch_bounds__(256) k_scores() {
    const int bh = blockIdx.z;
    const float* Q = g_q + (size_t)bh * Nn * HDm;
    const float* K = g_k + (size_t)bh * Nn * HDm;
    float* S = g_s + (size_t)bh * Nn * Nn;

    __shared__ __align__(16) float Qs[16][64];
    __shared__ __align__(16) float Ks[16][64];
    const int bm = blockIdx.y * 64;
    const int bn = blockIdx.x * 64;
    const int t  = threadIdx.x;
    const int lr = t >> 2;
    const int lk = (t & 3) * 4;
    const int tr = (t >> 4) * 4;
    const int tc = (t & 15) * 4;

    float acc[4][4];
#pragma unroll
    for (int i = 0; i < 4; i++)
#pragma unroll
        for (int j = 0; j < 4; j++) acc[i][j] = 0.f;

    for (int k0 = 0; k0 < HDm; k0 += 16) {
        float4 qv = *reinterpret_cast<const float4*>(Q + (size_t)(bm + lr) * HDm + k0 + lk);
        float4 kv = *reinterpret_cast<const float4*>(K + (size_t)(bn + lr) * HDm + k0 + lk);
        __syncthreads();
        Qs[lk + 0][lr] = qv.x; Qs[lk + 1][lr] = qv.y; Qs[lk + 2][lr] = qv.z; Qs[lk + 3][lr] = qv.w;
        Ks[lk + 0][lr] = kv.x; Ks[lk + 1][lr] = kv.y; Ks[lk + 2][lr] = kv.z; Ks[lk + 3][lr] = kv.w;
        __syncthreads();
#pragma unroll
        for (int kk = 0; kk < 16; kk++) {
            float a[4], b[4];
#pragma unroll
            for (int i = 0; i < 4; i++) a[i] = Qs[kk][tr + i];
#pragma unroll
            for (int j = 0; j < 4; j++) b[j] = Ks[kk][tc + j];
#pragma unroll
            for (int i = 0; i < 4; i++)
#pragma unroll
                for (int j = 0; j < 4; j++) acc[i][j] = fmaf(a[i], b[j], acc[i][j]);
        }
    }
#pragma unroll
    for (int i = 0; i < 4; i++)
#pragma unroll
        for (int j = 0; j < 4; j++)
            S[(size_t)(bm + tr + i) * Nn + bn + tc + j] = acc[i][j];
}

// ---------------------------------------------------------------------------
// K3: fused talking-heads mix + softmax + mix (unchanged)
// ---------------------------------------------------------------------------
__global__ void __launch_bounds__(576) k_mix_softmax(const float* __restrict__ Wl,
                                                     const float* __restrict__ bl,
                                                     const float* __restrict__ Ww,
                                                     const float* __restrict__ bw) {
    const int bm = blockIdx.x;
    const int b  = bm / Nn;
    const int m  = bm - b * Nn;
    const int n  = threadIdx.x;
    const int lane = threadIdx.x & 31;
    const int wp   = threadIdx.x >> 5;

    __shared__ float sWl[144], sWw[144], sbl[12], sbw[12];
    __shared__ float red[12][20];
    __shared__ float rowstat[12];

    if (threadIdx.x < 144) { sWl[threadIdx.x] = Wl[threadIdx.x]; sWw[threadIdx.x] = Ww[threadIdx.x]; }
    if (threadIdx.x < 12)  { sbl[threadIdx.x] = bl[threadIdx.x]; sbw[threadIdx.x] = bw[threadIdx.x]; }
    __syncthreads();

    const size_t base = ((size_t)(b * Hh) * Nn + m) * Nn + n;
    const size_t hstr = (size_t)Nn * Nn;

    float s[12];
#pragma unroll
    for (int h = 0; h < 12; h++) s[h] = g_s[base + (size_t)h * hstr];

    float a[12];
#pragma unroll
    for (int g = 0; g < 12; g++) {
        float acc = sbl[g];
#pragma unroll
        for (int h = 0; h < 12; h++) acc = fmaf(sWl[g * 12 + h], s[h], acc);
        a[g] = acc;
    }

#pragma unroll
    for (int g = 0; g < 12; g++) {
        float v = a[g];
#pragma unroll
        for (int o = 16; o > 0; o >>= 1) v = fmaxf(v, __shfl_xor_sync(0xffffffffu, v, o));
        if (lane == 0) red[g][wp] = v;
    }
    __syncthreads();
    if (threadIdx.x < 12) {
        float v = red[threadIdx.x][0];
        for (int w2 = 1; w2 < 18; w2++) v = fmaxf(v, red[threadIdx.x][w2]);
        rowstat[threadIdx.x] = v;
    }
    __syncthreads();

    float p[12];
#pragma unroll
    for (int g = 0; g < 12; g++) p[g] = __expf(a[g] - rowstat[g]);
    __syncthreads();

#pragma unroll
    for (int g = 0; g < 12; g++) {
        float v = p[g];
#pragma unroll
        for (int o = 16; o > 0; o >>= 1) v += __shfl_xor_sync(0xffffffffu, v, o);
        if (lane == 0) red[g][wp] = v;
    }
    __syncthreads();
    if (threadIdx.x < 12) {
        float v = 0.f;
        for (int w2 = 0; w2 < 18; w2++) v += red[threadIdx.x][w2];
        rowstat[threadIdx.x] = 1.0f / v;
    }
    __syncthreads();

#pragma unroll
    for (int g = 0; g < 12; g++) p[g] *= rowstat[g];

#pragma unroll
    for (int g = 0; g < 12; g++) {
        float acc = sbw[g];
#pragma unroll
        for (int h = 0; h < 12; h++) acc = fmaf(sWw[g * 12 + h], p[h], acc);
        g_s[base + (size_t)g * hstr] = acc;
    }
}

// ---------------------------------------------------------------------------
// K4: per (b,h): O[m,d] = sum_n P[m,n]*V[n,d]. Epilogue writes bf16 split.
// ---------------------------------------------------------------------------
__global__ void __launch_bounds__(256) k_pv() {
    const int bh = blockIdx.z;
    const int b  = bh / Hh;
    const int h  = bh - b * Hh;
    const float* P = g_s + (size_t)bh * Nn * Nn;
    const float* V = g_v + (size_t)bh * Nn * HDm;

    __shared__ __align__(16) float Ps[16][64];
    __shared__ __align__(16) float Vs[16][64];
    const int bm = blockIdx.y * 64;
    const int t  = threadIdx.x;
    const int pr = t >> 2;
    const int pk = (t & 3) * 4;
    const int vr = t >> 4;
    const int vc = (t & 15) * 4;
    const int tr = (t >> 4) * 4;
    const int tc = (t & 15) * 4;

    float acc[4][4];
#pragma unroll
    for (int i = 0; i < 4; i++)
#pragma unroll
        for (int j = 0; j < 4; j++) acc[i][j] = 0.f;

    for (int k0 = 0; k0 < Nn; k0 += 16) {
        float4 pv = *reinterpret_cast<const float4*>(P + (size_t)(bm + pr) * Nn + k0 + pk);
        float4 vv = *reinterpret_cast<const float4*>(V + (size_t)(k0 + vr) * HDm + vc);
        __syncthreads();
        Ps[pk + 0][pr] = pv.x; Ps[pk + 1][pr] = pv.y; Ps[pk + 2][pr] = pv.z; Ps[pk + 3][pr] = pv.w;
        *reinterpret_cast<float4*>(&Vs[vr][vc]) = vv;
        __syncthreads();
#pragma unroll
        for (int kk = 0; kk < 16; kk++) {
            float a[4], bx[4];
#pragma unroll
            for (int i = 0; i < 4; i++) a[i]  = Ps[kk][tr + i];
#pragma unroll
            for (int j = 0; j < 4; j++) bx[j] = Vs[kk][tc + j];
#pragma unroll
            for (int i = 0; i < 4; i++)
#pragma unroll
                for (int j = 0; j < 4; j++) acc[i][j] = fmaf(a[i], bx[j], acc[i][j]);
        }
    }
#pragma unroll
    for (int i = 0; i < 4; i++) {
        const int m = bm + tr + i;
#pragma unroll
        for (int j = 0; j < 4; j++) {
            const int d = tc + j;
            const size_t dst = (size_t)(b * Nn + m) * Cc + h * HDm + d;
            const float val = acc[i][j];
            __nv_bfloat16 hi = __float2bfloat16_rn(val);
            g_ohhi[dst] = hi;
            g_ohlo[dst] = __float2bfloat16_rn(val - __bfloat162float(hi));
        }
    }
}

// ---------------------------------------------------------------------------
extern "C" void kernel_launch(void* const* d_in, const int* in_sizes, int n_in,
                              void* d_out, int out_size) {
    const float* x     = (const float*)d_in[0];
    const float* Wqkv  = (const float*)d_in[1];
    const float* Wl    = (const float*)d_in[2];
    const float* bl    = (const float*)d_in[3];
    const float* Ww    = (const float*)d_in[4];
    const float* bw    = (const float*)d_in[5];
    const float* Wproj = (const float*)d_in[6];
    const float* bproj = (const float*)d_in[7];
    float* out = (float*)d_out;

    __nv_bfloat16 *xhi, *xlo, *wqhi, *wqlo, *wphi, *wplo, *ohhi, *ohlo;
    cudaGetSymbolAddress((void**)&xhi,  g_xhi);  cudaGetSymbolAddress((void**)&xlo,  g_xlo);
    cudaGetSymbolAddress((void**)&wqhi, g_wqhi); cudaGetSymbolAddress((void**)&wqlo, g_wqlo);
    cudaGetSymbolAddress((void**)&wphi, g_wphi); cudaGetSymbolAddress((void**)&wplo, g_wplo);
    cudaGetSymbolAddress((void**)&ohhi, g_ohhi); cudaGetSymbolAddress((void**)&ohlo, g_ohlo);

    const int nX  = BN * Cc;       // 7077888
    const int nWq = C3 * Cc;       // 1769472
    const int nWp = Cc * Cc;       // 589824
    k_split<<<(nX  + 255) / 256, 256>>>(x,     xhi,  xlo,  nX);
    k_split<<<(nWq + 255) / 256, 256>>>(Wqkv,  wqhi, wqlo, nWq);
    k_split<<<(nWp + 255) / 256, 256>>>(Wproj, wphi, wplo, nWp);

    k_gemm_bf16<0><<<dim3(C3 / 128, BN / 128), 256>>>(xhi, xlo, wqhi, wqlo, nullptr, nullptr);
    k_scores<<<dim3(Nn / 64, Nn / 64, Bb * Hh), 256>>>();
    k_mix_softmax<<<BN, 576>>>(Wl, bl, Ww, bw);
    k_pv<<<dim3(1, Nn / 64, Bb * Hh), 256>>>();
    k_gemm_bf16<1><<<dim3(Cc / 128, BN / 128), 256>>>(ohhi, ohlo, wphi, wplo, bproj, out);
}

// round 3
// speedup vs baseline: 1.7940x; 1.2471x over previous
#include <cuda_runtime.h>
#include <cuda_bf16.h>
#include <cstdint>

// ---------------------------------------------------------------------------
// TalkingHeadAttn (B=16, N=576, C=768, H=12, HD=64)
// R2: all GEMMs on mma.sync bf16 3-term split; cp.async pipelined qkv/proj.
// ---------------------------------------------------------------------------

#define Bb 16
#define Nn 576
#define Cc 768
#define Hh 12
#define HDm 64
#define BN (Bb * Nn)     // 9216
#define C3 (3 * Cc)      // 2304
#define BH (Bb * Hh)     // 192
#define QK_SCALE 0.125f

// ---- scratch -----------------------------------------------------------
__device__ float g_s[(size_t)BH * Nn * Nn];                        // 255 MB
__device__ __nv_bfloat16 g_qh[(size_t)BH * Nn * HDm], g_ql[(size_t)BH * Nn * HDm];
__device__ __nv_bfloat16 g_kh[(size_t)BH * Nn * HDm], g_kl[(size_t)BH * Nn * HDm];
__device__ __nv_bfloat16 g_vth[(size_t)BH * HDm * Nn], g_vtl[(size_t)BH * HDm * Nn]; // V^T [bh][d][n]
__device__ __nv_bfloat16 g_p2h[(size_t)BH * Nn * Nn], g_p2l[(size_t)BH * Nn * Nn];   // 127MB each
__device__ __nv_bfloat16 g_ohh[(size_t)BN * Cc], g_ohl[(size_t)BN * Cc];
__device__ __nv_bfloat16 g_xh[(size_t)BN * Cc],  g_xl[(size_t)BN * Cc];
__device__ __nv_bfloat16 g_wqh[(size_t)C3 * Cc], g_wql[(size_t)C3 * Cc];
__device__ __nv_bfloat16 g_wph[(size_t)Cc * Cc], g_wpl[(size_t)Cc * Cc];

// ---- helpers -----------------------------------------------------------
#define MMA_BF16(C, A, B)                                                     \
    asm volatile(                                                             \
        "mma.sync.aligned.m16n8k16.row.col.f32.bf16.bf16.f32 "                \
        "{%0,%1,%2,%3}, {%4,%5,%6,%7}, {%8,%9}, {%0,%1,%2,%3};\n"             \
        : "+f"((C)[0]), "+f"((C)[1]), "+f"((C)[2]), "+f"((C)[3])              \
        : "r"((A)[0]), "r"((A)[1]), "r"((A)[2]), "r"((A)[3]),                 \
          "r"((B)[0]), "r"((B)[1]))

__device__ __forceinline__ uint32_t smem_u32(const void* p) {
    return static_cast<uint32_t>(__cvta_generic_to_shared(p));
}
__device__ __forceinline__ void cp16(uint32_t dst, const void* src) {
    asm volatile("cp.async.cg.shared.global [%0], [%1], 16;\n" :: "r"(dst), "l"(src));
}
#define CP_COMMIT() asm volatile("cp.async.commit_group;\n")
#define CP_WAIT(n)  asm volatile("cp.async.wait_group %0;\n" :: "n"(n))

__device__ __forceinline__ void split_store(__nv_bfloat16* hi, __nv_bfloat16* lo,
                                            size_t idx, float v) {
    __nv_bfloat16 h = __float2bfloat16_rn(v);
    hi[idx] = h;
    lo[idx] = __float2bfloat16_rn(v - __bfloat162float(h));
}

// ---------------------------------------------------------------------------
__global__ void k_split(const float* __restrict__ src,
                        __nv_bfloat16* __restrict__ hi,
                        __nv_bfloat16* __restrict__ lo, int n) {
    int i = blockIdx.x * blockDim.x + threadIdx.x;
    if (i < n) {
        float x = src[i];
        __nv_bfloat16 h = __float2bfloat16_rn(x);
        hi[i] = h;
        lo[i] = __float2bfloat16_rn(x - __bfloat162float(h));
    }
}

// ---------------------------------------------------------------------------
// GEMM C[m,l] = sum_k A[m,k]*W[l,k], K=768. CTA 128x64, BK=32, 3-stage cp.async.
// 256 thr, 8 warps (4m x 2n), warp tile 32x32. MODE0: qkv scatter; MODE1: proj.
// dyn smem: Ah[3][128][40], Al, Bh[3][64][40], Bl  (92160 B)
// ---------------------------------------------------------------------------
#define GEMM_SMEM (size_t)((3 * 128 * 40 + 3 * 128 * 40 + 3 * 64 * 40 + 3 * 64 * 40) * 2)

template <int MODE>
__global__ void __launch_bounds__(256, 2) k_gemm(
    const __nv_bfloat16* __restrict__ Ah_, const __nv_bfloat16* __restrict__ Al_,
    const __nv_bfloat16* __restrict__ Wh_, const __nv_bfloat16* __restrict__ Wl_,
    const float* __restrict__ bias, float* __restrict__ out) {

    extern __shared__ __nv_bfloat16 smem[];
    __nv_bfloat16* sAh = smem;                        // 3*128*40
    __nv_bfloat16* sAl = sAh + 3 * 128 * 40;
    __nv_bfloat16* sBh = sAl + 3 * 128 * 40;          // 3*64*40
    __nv_bfloat16* sBl = sBh + 3 * 64 * 40;

    const int bm = blockIdx.y * 128;
    const int blb = blockIdx.x * 64;
    const int t = threadIdx.x, lane = t & 31, warp = t >> 5;
    const int gid = lane >> 2, tig = lane & 3;
    const int wm = (warp >> 1) * 32, wn = (warp & 1) * 32;

    const int arow = t >> 1, acol = (t & 1) * 16;
    const int brow = t >> 2, bcol = (t & 3) * 8;

    const __nv_bfloat16* gAh = Ah_ + (size_t)(bm + arow) * Cc + acol;
    const __nv_bfloat16* gAl = Al_ + (size_t)(bm + arow) * Cc + acol;
    const __nv_bfloat16* gBh = Wh_ + (size_t)(blb + brow) * Cc + bcol;
    const __nv_bfloat16* gBl = Wl_ + (size_t)(blb + brow) * Cc + bcol;

    const uint32_t dAh = smem_u32(sAh) + (uint32_t)(arow * 40 + acol) * 2;
    const uint32_t dAl = smem_u32(sAl) + (uint32_t)(arow * 40 + acol) * 2;
    const uint32_t dBh = smem_u32(sBh) + (uint32_t)(brow * 40 + bcol) * 2;
    const uint32_t dBl = smem_u32(sBl) + (uint32_t)(brow * 40 + bcol) * 2;
    const uint32_t stA = 128 * 40 * 2, stB = 64 * 40 * 2;

    auto issue = [&](int s, int kt) {
        const int k0 = kt * 32;
        cp16(dAh + s * stA,      gAh + k0);
        cp16(dAh + s * stA + 16, gAh + k0 + 8);
        cp16(dAl + s * stA,      gAl + k0);
        cp16(dAl + s * stA + 16, gAl + k0 + 8);
        cp16(dBh + s * stB,      gBh + k0);
        cp16(dBl + s * stB,      gBl + k0);
        CP_COMMIT();
    };

    float acc[2][4][4];
#pragma unroll
    for (int mt = 0; mt < 2; mt++)
#pragma unroll
        for (int nt = 0; nt < 4; nt++)
#pragma unroll
            for (int r = 0; r < 4; r++) acc[mt][nt][r] = 0.f;

    const int KT = Cc / 32;   // 24
    issue(0, 0);
    issue(1, 1);

    for (int kt = 0; kt < KT; kt++) {
        const int st = kt % 3;
        if (kt + 1 < KT) { CP_WAIT(1); } else { CP_WAIT(0); }
        __syncthreads();
        if (kt + 2 < KT) issue((kt + 2) % 3, kt + 2);

        const __nv_bfloat16* pAh = sAh + st * 128 * 40;
        const __nv_bfloat16* pAl = sAl + st * 128 * 40;
        const __nv_bfloat16* pBh = sBh + st * 64 * 40;
        const __nv_bfloat16* pBl = sBl + st * 64 * 40;
#pragma unroll
        for (int kk = 0; kk < 32; kk += 16) {
            uint32_t ah[2][4], al[2][4];
#pragma unroll
            for (int mt = 0; mt < 2; mt++) {
                const int r0 = wm + mt * 16 + gid;
                ah[mt][0] = *(const uint32_t*)&pAh[r0 * 40 + kk + tig * 2];
                ah[mt][1] = *(const uint32_t*)&pAh[(r0 + 8) * 40 + kk + tig * 2];
                ah[mt][2] = *(const uint32_t*)&pAh[r0 * 40 + kk + tig * 2 + 8];
                ah[mt][3] = *(const uint32_t*)&pAh[(r0 + 8) * 40 + kk + tig * 2 + 8];
                al[mt][0] = *(const uint32_t*)&pAl[r0 * 40 + kk + tig * 2];
                al[mt][1] = *(const uint32_t*)&pAl[(r0 + 8) * 40 + kk + tig * 2];
                al[mt][2] = *(const uint32_t*)&pAl[r0 * 40 + kk + tig * 2 + 8];
                al[mt][3] = *(const uint32_t*)&pAl[(r0 + 8) * 40 + kk + tig * 2 + 8];
            }
            uint32_t bh2[4][2], bl2[4][2];
#pragma unroll
            for (int nt = 0; nt < 4; nt++) {
                const int c0 = wn + nt * 8 + gid;
                bh2[nt][0] = *(const uint32_t*)&pBh[c0 * 40 + kk + tig * 2];
                bh2[nt][1] = *(const uint32_t*)&pBh[c0 * 40 + kk + tig * 2 + 8];
                bl2[nt][0] = *(const uint32_t*)&pBl[c0 * 40 + kk + tig * 2];
                bl2[nt][1] = *(const uint32_t*)&pBl[c0 * 40 + kk + tig * 2 + 8];
            }
#pragma unroll
            for (int mt = 0; mt < 2; mt++)
#pragma unroll
                for (int nt = 0; nt < 4; nt++) {
                    MMA_BF16(acc[mt][nt], ah[mt], bh2[nt]);
                    MMA_BF16(acc[mt][nt], ah[mt], bl2[nt]);
                    MMA_BF16(acc[mt][nt], al[mt], bh2[nt]);
                }
        }
    }

    // epilogue
#pragma unroll
    for (int mt = 0; mt < 2; mt++) {
#pragma unroll
        for (int nt = 0; nt < 4; nt++) {
#pragma unroll
            for (int r = 0; r < 4; r++) {
                const int m = bm + wm + mt * 16 + gid + ((r >= 2) ? 8 : 0);
                const int l = blb + wn + nt * 8 + tig * 2 + (r & 1);
                const float v = acc[mt][nt][r];
                if (MODE == 0) {
                    const int bi = m / Nn, ni = m - bi * Nn;
                    const int sI = l / Cc, rem = l - sI * Cc;
                    const int h = rem >> 6, d = rem & 63;
                    const int bh = bi * Hh + h;
                    if (sI == 0) {
                        split_store(g_qh, g_ql, ((size_t)bh * Nn + ni) * HDm + d, v * QK_SCALE);
                    } else if (sI == 1) {
                        split_store(g_kh, g_kl, ((size_t)bh * Nn + ni) * HDm + d, v);
                    } else {
                        split_store(g_vth, g_vtl, ((size_t)bh * HDm + d) * Nn + ni, v);
                    }
                } else {
                    out[(size_t)m * Cc + l] = v + bias[l];
                }
            }
        }
    }
}

// ---------------------------------------------------------------------------
// scores: per (b,h): S[m,n] = q[m,:]·k[n,:]. CTA 64x64, K=64 one-shot.
// 128 thr = 4 warps (2m x 2n), warp 32x32.
// ---------------------------------------------------------------------------
__global__ void __launch_bounds__(128) k_scores() {
    __shared__ __nv_bfloat16 sQh[64][72], sQl[64][72], sKh[64][72], sKl[64][72];
    const int bh = blockIdx.z;
    const int bm = blockIdx.y * 64, bn = blockIdx.x * 64;
    const int t = threadIdx.x, lane = t & 31, warp = t >> 5;
    const int gid = lane >> 2, tig = lane & 3;
    const int wm = (warp >> 1) * 32, wn = (warp & 1) * 32;

    const int row = t >> 1, cs = (t & 1) * 32;
#pragma unroll
    for (int j = 0; j < 4; j++) {
        const int col = cs + j * 8;
        *(uint4*)&sQh[row][col] = *(const uint4*)&g_qh[((size_t)bh * Nn + bm + row) * HDm + col];
        *(uint4*)&sQl[row][col] = *(const uint4*)&g_ql[((size_t)bh * Nn + bm + row) * HDm + col];
        *(uint4*)&sKh[row][col] = *(const uint4*)&g_kh[((size_t)bh * Nn + bn + row) * HDm + col];
        *(uint4*)&sKl[row][col] = *(const uint4*)&g_kl[((size_t)bh * Nn + bn + row) * HDm + col];
    }
    __syncthreads();

    float acc[2][4][4];
#pragma unroll
    for (int mt = 0; mt < 2; mt++)
#pragma unroll
        for (int nt = 0; nt < 4; nt++)
#pragma unroll
            for (int r = 0; r < 4; r++) acc[mt][nt][r] = 0.f;

#pragma unroll
    for (int kk = 0; kk < 64; kk += 16) {
        uint32_t ah[2][4], al[2][4];
#pragma unroll
        for (int mt = 0; mt < 2; mt++) {
            const int r0 = wm + mt * 16 + gid;
            ah[mt][0] = *(const uint32_t*)&sQh[r0][kk + tig * 2];
            ah[mt][1] = *(const uint32_t*)&sQh[r0 + 8][kk + tig * 2];
            ah[mt][2] = *(const uint32_t*)&sQh[r0][kk + tig * 2 + 8];
            ah[mt][3] = *(const uint32_t*)&sQh[r0 + 8][kk + tig * 2 + 8];
            al[mt][0] = *(const uint32_t*)&sQl[r0][kk + tig * 2];
            al[mt][1] = *(const uint32_t*)&sQl[r0 + 8][kk + tig * 2];
            al[mt][2] = *(const uint32_t*)&sQl[r0][kk + tig * 2 + 8];
            al[mt][3] = *(const uint32_t*)&sQl[r0 + 8][kk + tig * 2 + 8];
        }
        uint32_t bh2[4][2], bl2[4][2];
#pragma unroll
        for (int nt = 0; nt < 4; nt++) {
            const int c0 = wn + nt * 8 + gid;
            bh2[nt][0] = *(const uint32_t*)&sKh[c0][kk + tig * 2];
            bh2[nt][1] = *(const uint32_t*)&sKh[c0][kk + tig * 2 + 8];
            bl2[nt][0] = *(const uint32_t*)&sKl[c0][kk + tig * 2];
            bl2[nt][1] = *(const uint32_t*)&sKl[c0][kk + tig * 2 + 8];
        }
#pragma unroll
        for (int mt = 0; mt < 2; mt++)
#pragma unroll
            for (int nt = 0; nt < 4; nt++) {
                MMA_BF16(acc[mt][nt], ah[mt], bh2[nt]);
                MMA_BF16(acc[mt][nt], ah[mt], bl2[nt]);
                MMA_BF16(acc[mt][nt], al[mt], bh2[nt]);
            }
    }

#pragma unroll
    for (int mt = 0; mt < 2; mt++)
#pragma unroll
        for (int nt = 0; nt < 4; nt++)
#pragma unroll
            for (int rp = 0; rp < 2; rp++) {
                const int m = bm + wm + mt * 16 + gid + rp * 8;
                const int n = bn + wn + nt * 8 + tig * 2;
                float2 v = make_float2(acc[mt][nt][rp * 2], acc[mt][nt][rp * 2 + 1]);
                *(float2*)&g_s[((size_t)bh * Nn + m) * Nn + n] = v;
            }
}

// ---------------------------------------------------------------------------
// fused talking-heads mix + softmax + mix; writes P2 as bf16 split
// ---------------------------------------------------------------------------
__global__ void __launch_bounds__(576) k_mix_softmax(const float* __restrict__ Wl,
                                                     const float* __restrict__ bl,
                                                     const float* __restrict__ Ww,
                                                     const float* __restrict__ bw) {
    const int bm = blockIdx.x;
    const int b = bm / Nn, m = bm - b * Nn;
    const int n = threadIdx.x;
    const int lane = threadIdx.x & 31, wp = threadIdx.x >> 5;

    __shared__ float sWl[144], sWw[144], sbl[12], sbw[12];
    __shared__ float red[12][20];
    __shared__ float rowstat[12];

    if (threadIdx.x < 144) { sWl[threadIdx.x] = Wl[threadIdx.x]; sWw[threadIdx.x] = Ww[threadIdx.x]; }
    if (threadIdx.x < 12)  { sbl[threadIdx.x] = bl[threadIdx.x]; sbw[threadIdx.x] = bw[threadIdx.x]; }
    __syncthreads();

    const size_t base = ((size_t)(b * Hh) * Nn + m) * Nn + n;
    const size_t hstr = (size_t)Nn * Nn;

    float s[12];
#pragma unroll
    for (int h = 0; h < 12; h++) s[h] = g_s[base + (size_t)h * hstr];

    float a[12];
#pragma unroll
    for (int g = 0; g < 12; g++) {
        float acc = sbl[g];
#pragma unroll
        for (int h = 0; h < 12; h++) acc = fmaf(sWl[g * 12 + h], s[h], acc);
        a[g] = acc;
    }

#pragma unroll
    for (int g = 0; g < 12; g++) {
        float v = a[g];
#pragma unroll
        for (int o = 16; o > 0; o >>= 1) v = fmaxf(v, __shfl_xor_sync(0xffffffffu, v, o));
        if (lane == 0) red[g][wp] = v;
    }
    __syncthreads();
    if (threadIdx.x < 12) {
        float v = red[threadIdx.x][0];
        for (int w2 = 1; w2 < 18; w2++) v = fmaxf(v, red[threadIdx.x][w2]);
        rowstat[threadIdx.x] = v;
    }
    __syncthreads();

    float p[12];
#pragma unroll
    for (int g = 0; g < 12; g++) p[g] = __expf(a[g] - rowstat[g]);
    __syncthreads();

#pragma unroll
    for (int g = 0; g < 12; g++) {
        float v = p[g];
#pragma unroll
        for (int o = 16; o > 0; o >>= 1) v += __shfl_xor_sync(0xffffffffu, v, o);
        if (lane == 0) red[g][wp] = v;
    }
    __syncthreads();
    if (threadIdx.x < 12) {
        float v = 0.f;
        for (int w2 = 0; w2 < 18; w2++) v += red[threadIdx.x][w2];
        rowstat[threadIdx.x] = 1.0f / v;
    }
    __syncthreads();

#pragma unroll
    for (int g = 0; g < 12; g++) p[g] *= rowstat[g];

#pragma unroll
    for (int g = 0; g < 12; g++) {
        float acc = sbw[g];
#pragma unroll
        for (int h = 0; h < 12; h++) acc = fmaf(sWw[g * 12 + h], p[h], acc);
        split_store(g_p2h, g_p2l, base + (size_t)g * hstr, acc);
    }
}

// ---------------------------------------------------------------------------
// PV: per (b,h): O[m,d] = sum_n P2[m,n] Vt[d,n]. CTA 64x64, K=576, BK=32,
// 3-stage cp.async, 128 thr = 4 warps (2m x 2d), warp 32x32.
// dyn smem: Ph[3][64][40], Pl, Vh, Vl (61440 B)
// ---------------------------------------------------------------------------
#define PV_SMEM (size_t)(4 * 3 * 64 * 40 * 2)

__global__ void __launch_bounds__(128, 3) k_pv() {
    extern __shared__ __nv_bfloat16 smem[];
    __nv_bfloat16* sPh = smem;
    __nv_bfloat16* sPl = sPh + 3 * 64 * 40;
    __nv_bfloat16* sVh = sPl + 3 * 64 * 40;
    __nv_bfloat16* sVl = sVh + 3 * 64 * 40;

    const int bh = blockIdx.y;
    const int bm = blockIdx.x * 64;
    const int t = threadIdx.x, lane = t & 31, warp = t >> 5;
    const int gid = lane >> 2, tig = lane & 3;
    const int wm = (warp >> 1) * 32, wn = (warp & 1) * 32;

    const int row = t >> 1, cs = (t & 1) * 16;
    const __nv_bfloat16* gPh = g_p2h + ((size_t)bh * Nn + bm + row) * Nn + cs;
    const __nv_bfloat16* gPl = g_p2l + ((size_t)bh * Nn + bm + row) * Nn + cs;
    const __nv_bfloat16* gVh = g_vth + ((size_t)bh * HDm + row) * Nn + cs;
    const __nv_bfloat16* gVl = g_vtl + ((size_t)bh * HDm + row) * Nn + cs;

    const uint32_t dPh = smem_u32(sPh) + (uint32_t)(row * 40 + cs) * 2;
    const uint32_t dPl = smem_u32(sPl) + (uint32_t)(row * 40 + cs) * 2;
    const uint32_t dVh = smem_u32(sVh) + (uint32_t)(row * 40 + cs) * 2;
    const uint32_t dVl = smem_u32(sVl) + (uint32_t)(row * 40 + cs) * 2;
    const uint32_t stg = 64 * 40 * 2;

    auto issue = [&](int s, int kt) {
        const int k0 = kt * 32;
        cp16(dPh + s * stg,      gPh + k0);
        cp16(dPh + s * stg + 16, gPh + k0 + 8);
        cp16(dPl + s * stg,      gPl + k0);
        cp16(dPl + s * stg + 16, gPl + k0 + 8);
        cp16(dVh + s * stg,      gVh + k0);
        cp16(dVh + s * stg + 16, gVh + k0 + 8);
        cp16(dVl + s * stg,      gVl + k0);
        cp16(dVl + s * stg + 16, gVl + k0 + 8);
        CP_COMMIT();
    };

    float acc[2][4][4];
#pragma unroll
    for (int mt = 0; mt < 2; mt++)
#pragma unroll
        for (int nt = 0; nt < 4; nt++)
#pragma unroll
            for (int r = 0; r < 4; r++) acc[mt][nt][r] = 0.f;

    const int KT = Nn / 32;   // 18
    issue(0, 0);
    issue(1, 1);

    for (int kt = 0; kt < KT; kt++) {
        const int st = kt % 3;
        if (kt + 1 < KT) { CP_WAIT(1); } else { CP_WAIT(0); }
        __syncthreads();
        if (kt + 2 < KT) issue((kt + 2) % 3, kt + 2);

        const __nv_bfloat16* pPh = sPh + st * 64 * 40;
        const __nv_bfloat16* pPl = sPl + st * 64 * 40;
        const __nv_bfloat16* pVh = sVh + st * 64 * 40;
        const __nv_bfloat16* pVl = sVl + st * 64 * 40;
#pragma unroll
        for (int kk = 0; kk < 32; kk += 16) {
            uint32_t ah[2][4], al[2][4];
#pragma unroll
            for (int mt = 0; mt < 2; mt++) {
                const int r0 = wm + mt * 16 + gid;
                ah[mt][0] = *(const uint32_t*)&pPh[r0 * 40 + kk + tig * 2];
                ah[mt][1] = *(const uint32_t*)&pPh[(r0 + 8) * 40 + kk + tig * 2];
                ah[mt][2] = *(const uint32_t*)&pPh[r0 * 40 + kk + tig * 2 + 8];
                ah[mt][3] = *(const uint32_t*)&pPh[(r0 + 8) * 40 + kk + tig * 2 + 8];
                al[mt][0] = *(const uint32_t*)&pPl[r0 * 40 + kk + tig * 2];
                al[mt][1] = *(const uint32_t*)&pPl[(r0 + 8) * 40 + kk + tig * 2];
                al[mt][2] = *(const uint32_t*)&pPl[r0 * 40 + kk + tig * 2 + 8];
                al[mt][3] = *(const uint32_t*)&pPl[(r0 + 8) * 40 + kk + tig * 2 + 8];
            }
            uint32_t bh2[4][2], bl2[4][2];
#pragma unroll
            for (int nt = 0; nt < 4; nt++) {
                const int c0 = wn + nt * 8 + gid;
                bh2[nt][0] = *(const uint32_t*)&pVh[c0 * 40 + kk + tig * 2];
                bh2[nt][1] = *(const uint32_t*)&pVh[c0 * 40 + kk + tig * 2 + 8];
                bl2[nt][0] = *(const uint32_t*)&pVl[c0 * 40 + kk + tig * 2];
                bl2[nt][1] = *(const uint32_t*)&pVl[c0 * 40 + kk + tig * 2 + 8];
            }
#pragma unroll
            for (int mt = 0; mt < 2; mt++)
#pragma unroll
                for (int nt = 0; nt < 4; nt++) {
                    MMA_BF16(acc[mt][nt], ah[mt], bh2[nt]);
                    MMA_BF16(acc[mt][nt], ah[mt], bl2[nt]);
                    MMA_BF16(acc[mt][nt], al[mt], bh2[nt]);
                }
        }
    }

    // epilogue -> g_oh bf16 split, row = b*Nn+m, col = h*64+d
    const int b = bh / Hh, h = bh - b * Hh;
#pragma unroll
    for (int mt = 0; mt < 2; mt++)
#pragma unroll
        for (int nt = 0; nt < 4; nt++)
#pragma unroll
            for (int rp = 0; rp < 2; rp++) {
                const int m = bm + wm + mt * 16 + gid + rp * 8;
                const int d = wn + nt * 8 + tig * 2;
                const size_t idx = ((size_t)(b * Nn + m)) * Cc + h * HDm + d;
                const float v0 = acc[mt][nt][rp * 2];
                const float v1 = acc[mt][nt][rp * 2 + 1];
                __nv_bfloat16 h0 = __float2bfloat16_rn(v0);
                __nv_bfloat16 h1 = __float2bfloat16_rn(v1);
                __nv_bfloat162 hp; hp.x = h0; hp.y = h1;
                __nv_bfloat162 lp;
                lp.x = __float2bfloat16_rn(v0 - __bfloat162float(h0));
                lp.y = __float2bfloat16_rn(v1 - __bfloat162float(h1));
                *(__nv_bfloat162*)&g_ohh[idx] = hp;
                *(__nv_bfloat162*)&g_ohl[idx] = lp;
            }
}

// ---------------------------------------------------------------------------
extern "C" void kernel_launch(void* const* d_in, const int* in_sizes, int n_in,
                              void* d_out, int out_size) {
    const float* x     = (const float*)d_in[0];
    const float* Wqkv  = (const float*)d_in[1];
    const float* Wl    = (const float*)d_in[2];
    const float* bl    = (const float*)d_in[3];
    const float* Ww    = (const float*)d_in[4];
    const float* bw    = (const float*)d_in[5];
    const float* Wproj = (const float*)d_in[6];
    const float* bproj = (const float*)d_in[7];
    float* out = (float*)d_out;

    __nv_bfloat16 *xh, *xl, *wqh, *wql, *wph, *wpl, *ohh, *ohl;
    cudaGetSymbolAddress((void**)&xh,  g_xh);  cudaGetSymbolAddress((void**)&xl,  g_xl);
    cudaGetSymbolAddress((void**)&wqh, g_wqh); cudaGetSymbolAddress((void**)&wql, g_wql);
    cudaGetSymbolAddress((void**)&wph, g_wph); cudaGetSymbolAddress((void**)&wpl, g_wpl);
    cudaGetSymbolAddress((void**)&ohh, g_ohh); cudaGetSymbolAddress((void**)&ohl, g_ohl);

    cudaFuncSetAttribute(k_gemm<0>, cudaFuncAttributeMaxDynamicSharedMemorySize, (int)GEMM_SMEM);
    cudaFuncSetAttribute(k_gemm<1>, cudaFuncAttributeMaxDynamicSharedMemorySize, (int)GEMM_SMEM);
    cudaFuncSetAttribute(k_pv,      cudaFuncAttributeMaxDynamicSharedMemorySize, (int)PV_SMEM);

    const int nX  = BN * Cc;
    const int nWq = C3 * Cc;
    const int nWp = Cc * Cc;
    k_split<<<(nX  + 255) / 256, 256>>>(x,     xh,  xl,  nX);
    k_split<<<(nWq + 255) / 256, 256>>>(Wqkv,  wqh, wql, nWq);
    k_split<<<(nWp + 255) / 256, 256>>>(Wproj, wph, wpl, nWp);

    k_gemm<0><<<dim3(C3 / 64, BN / 128), 256, GEMM_SMEM>>>(xh, xl, wqh, wql, nullptr, nullptr);
    k_scores<<<dim3(Nn / 64, Nn / 64, BH), 128>>>();
    k_mix_softmax<<<BN, 576>>>(Wl, bl, Ww, bw);
    k_pv<<<dim3(Nn / 64, BH), 128, PV_SMEM>>>();
    k_gemm<1><<<dim3(Cc / 64, BN / 128), 256, GEMM_SMEM>>>(ohh, ohl, wph, wpl, bproj, out);
}

// round 6
// speedup vs baseline: 1.8472x; 1.0297x over previous
#include <cuda_runtime.h>
#include <cuda_bf16.h>
#include <cstdint>

// ---------------------------------------------------------------------------
// TalkingHeadAttn (B=16, N=576, C=768, H=12, HD=64)
// R6 (resubmit of R5; container infra failed before execution):
//     legacy mma.sync bf16 3-term split everywhere (tcgen05 unavailable:
//     harness compiles PTX at .target sm_100 without the 'a' feature set).
//     qkv/proj: 128x64 cp.async pipelined GEMMs (at the mma.sync cap).
//     scores:   192x64 one-shot K=64 tiles, 384 thr.
//     pv:       192x64 tiles, K=576 streamed, 3-stage cp.async, 384 thr.
// ---------------------------------------------------------------------------

#define Bb 16
#define Nn 576
#define Cc 768
#define Hh 12
#define HDm 64
#define BN (Bb * Nn)     // 9216
#define C3 (3 * Cc)      // 2304
#define BH (Bb * Hh)     // 192
#define QK_SCALE 0.125f

// ---- scratch -----------------------------------------------------------
__device__ float g_s[(size_t)BH * Nn * Nn];                        // 255 MB
__device__ __nv_bfloat16 g_qh[(size_t)BH * Nn * HDm], g_ql[(size_t)BH * Nn * HDm];
__device__ __nv_bfloat16 g_kh[(size_t)BH * Nn * HDm], g_kl[(size_t)BH * Nn * HDm];
__device__ __nv_bfloat16 g_vth[(size_t)BH * HDm * Nn], g_vtl[(size_t)BH * HDm * Nn];
__device__ __nv_bfloat16 g_p2h[(size_t)BH * Nn * Nn], g_p2l[(size_t)BH * Nn * Nn];
__device__ __nv_bfloat16 g_ohh[(size_t)BN * Cc], g_ohl[(size_t)BN * Cc];
__device__ __nv_bfloat16 g_xh[(size_t)BN * Cc],  g_xl[(size_t)BN * Cc];
__device__ __nv_bfloat16 g_wqh[(size_t)C3 * Cc], g_wql[(size_t)C3 * Cc];
__device__ __nv_bfloat16 g_wph[(size_t)Cc * Cc], g_wpl[(size_t)Cc * Cc];

// ---- helpers -----------------------------------------------------------
#define MMA_BF16(C, A, B)                                                     \
    asm volatile(                                                             \
        "mma.sync.aligned.m16n8k16.row.col.f32.bf16.bf16.f32 "                \
        "{%0,%1,%2,%3}, {%4,%5,%6,%7}, {%8,%9}, {%0,%1,%2,%3};\n"             \
        : "+f"((C)[0]), "+f"((C)[1]), "+f"((C)[2]), "+f"((C)[3])              \
        : "r"((A)[0]), "r"((A)[1]), "r"((A)[2]), "r"((A)[3]),                 \
          "r"((B)[0]), "r"((B)[1]))

__device__ __forceinline__ uint32_t smem_u32(const void* p) {
    return static_cast<uint32_t>(__cvta_generic_to_shared(p));
}
__device__ __forceinline__ void cp16(uint32_t dst, const void* src) {
    asm volatile("cp.async.cg.shared.global [%0], [%1], 16;\n" :: "r"(dst), "l"(src));
}
#define CP_COMMIT() asm volatile("cp.async.commit_group;\n")
#define CP_WAIT(n)  asm volatile("cp.async.wait_group %0;\n" :: "n"(n))

__device__ __forceinline__ void split_store(__nv_bfloat16* hi, __nv_bfloat16* lo,
                                            size_t idx, float v) {
    __nv_bfloat16 h = __float2bfloat16_rn(v);
    hi[idx] = h;
    lo[idx] = __float2bfloat16_rn(v - __bfloat162float(h));
}

// ---------------------------------------------------------------------------
__global__ void k_split(const float* __restrict__ src,
                        __nv_bfloat16* __restrict__ hi,
                        __nv_bfloat16* __restrict__ lo, int n) {
    int i = blockIdx.x * blockDim.x + threadIdx.x;
    if (i < n) {
        float x = src[i];
        __nv_bfloat16 h = __float2bfloat16_rn(x);
        hi[i] = h;
        lo[i] = __float2bfloat16_rn(x - __bfloat162float(h));
    }
}

// ---------------------------------------------------------------------------
// GEMM C[m,l] = sum_k A[m,k]*W[l,k], K=768. CTA 128x64, BK=32, 3-stage cp.async.
// 256 thr, 8 warps (4m x 2n), warp tile 32x32. MODE0: qkv scatter; MODE1: proj.
// ---------------------------------------------------------------------------
#define GEMM_SMEM (size_t)((3 * 128 * 40 + 3 * 128 * 40 + 3 * 64 * 40 + 3 * 64 * 40) * 2)

template <int MODE>
__global__ void __launch_bounds__(256, 2) k_gemm(
    const __nv_bfloat16* __restrict__ Ah_, const __nv_bfloat16* __restrict__ Al_,
    const __nv_bfloat16* __restrict__ Wh_, const __nv_bfloat16* __restrict__ Wl_,
    const float* __restrict__ bias, float* __restrict__ out) {

    extern __shared__ __nv_bfloat16 smem[];
    __nv_bfloat16* sAh = smem;
    __nv_bfloat16* sAl = sAh + 3 * 128 * 40;
    __nv_bfloat16* sBh = sAl + 3 * 128 * 40;
    __nv_bfloat16* sBl = sBh + 3 * 64 * 40;

    const int bm = blockIdx.y * 128;
    const int blb = blockIdx.x * 64;
    const int t = threadIdx.x, lane = t & 31, warp = t >> 5;
    const int gid = lane >> 2, tig = lane & 3;
    const int wm = (warp >> 1) * 32, wn = (warp & 1) * 32;

    const int arow = t >> 1, acol = (t & 1) * 16;
    const int brow = t >> 2, bcol = (t & 3) * 8;

    const __nv_bfloat16* gAh = Ah_ + (size_t)(bm + arow) * Cc + acol;
    const __nv_bfloat16* gAl = Al_ + (size_t)(bm + arow) * Cc + acol;
    const __nv_bfloat16* gBh = Wh_ + (size_t)(blb + brow) * Cc + bcol;
    const __nv_bfloat16* gBl = Wl_ + (size_t)(blb + brow) * Cc + bcol;

    const uint32_t dAh = smem_u32(sAh) + (uint32_t)(arow * 40 + acol) * 2;
    const uint32_t dAl = smem_u32(sAl) + (uint32_t)(arow * 40 + acol) * 2;
    const uint32_t dBh = smem_u32(sBh) + (uint32_t)(brow * 40 + bcol) * 2;
    const uint32_t dBl = smem_u32(sBl) + (uint32_t)(brow * 40 + bcol) * 2;
    const uint32_t stA = 128 * 40 * 2, stB = 64 * 40 * 2;

    auto issue = [&](int s, int kt) {
        const int k0 = kt * 32;
        cp16(dAh + s * stA,      gAh + k0);
        cp16(dAh + s * stA + 16, gAh + k0 + 8);
        cp16(dAl + s * stA,      gAl + k0);
        cp16(dAl + s * stA + 16, gAl + k0 + 8);
        cp16(dBh + s * stB,      gBh + k0);
        cp16(dBl + s * stB,      gBl + k0);
        CP_COMMIT();
    };

    float acc[2][4][4];
#pragma unroll
    for (int mt = 0; mt < 2; mt++)
#pragma unroll
        for (int nt = 0; nt < 4; nt++)
#pragma unroll
            for (int r = 0; r < 4; r++) acc[mt][nt][r] = 0.f;

    const int KT = Cc / 32;   // 24
    issue(0, 0);
    issue(1, 1);

    for (int kt = 0; kt < KT; kt++) {
        const int st = kt % 3;
        if (kt + 1 < KT) { CP_WAIT(1); } else { CP_WAIT(0); }
        __syncthreads();
        if (kt + 2 < KT) issue((kt + 2) % 3, kt + 2);

        const __nv_bfloat16* pAh = sAh + st * 128 * 40;
        const __nv_bfloat16* pAl = sAl + st * 128 * 40;
        const __nv_bfloat16* pBh = sBh + st * 64 * 40;
        const __nv_bfloat16* pBl = sBl + st * 64 * 40;
#pragma unroll
        for (int kk = 0; kk < 32; kk += 16) {
            uint32_t ah[2][4], al[2][4];
#pragma unroll
            for (int mt = 0; mt < 2; mt++) {
                const int r0 = wm + mt * 16 + gid;
                ah[mt][0] = *(const uint32_t*)&pAh[r0 * 40 + kk + tig * 2];
                ah[mt][1] = *(const uint32_t*)&pAh[(r0 + 8) * 40 + kk + tig * 2];
                ah[mt][2] = *(const uint32_t*)&pAh[r0 * 40 + kk + tig * 2 + 8];
                ah[mt][3] = *(const uint32_t*)&pAh[(r0 + 8) * 40 + kk + tig * 2 + 8];
                al[mt][0] = *(const uint32_t*)&pAl[r0 * 40 + kk + tig * 2];
                al[mt][1] = *(const uint32_t*)&pAl[(r0 + 8) * 40 + kk + tig * 2];
                al[mt][2] = *(const uint32_t*)&pAl[r0 * 40 + kk + tig * 2 + 8];
                al[mt][3] = *(const uint32_t*)&pAl[(r0 + 8) * 40 + kk + tig * 2 + 8];
            }
            uint32_t bh2[4][2], bl2[4][2];
#pragma unroll
            for (int nt = 0; nt < 4; nt++) {
                const int c0 = wn + nt * 8 + gid;
                bh2[nt][0] = *(const uint32_t*)&pBh[c0 * 40 + kk + tig * 2];
                bh2[nt][1] = *(const uint32_t*)&pBh[c0 * 40 + kk + tig * 2 + 8];
                bl2[nt][0] = *(const uint32_t*)&pBl[c0 * 40 + kk + tig * 2];
                bl2[nt][1] = *(const uint32_t*)&pBl[c0 * 40 + kk + tig * 2 + 8];
            }
#pragma unroll
            for (int mt = 0; mt < 2; mt++)
#pragma unroll
                for (int nt = 0; nt < 4; nt++) {
                    MMA_BF16(acc[mt][nt], ah[mt], bh2[nt]);
                    MMA_BF16(acc[mt][nt], ah[mt], bl2[nt]);
                    MMA_BF16(acc[mt][nt], al[mt], bh2[nt]);
                }
        }
    }

#pragma unroll
    for (int mt = 0; mt < 2; mt++) {
#pragma unroll
        for (int nt = 0; nt < 4; nt++) {
#pragma unroll
            for (int r = 0; r < 4; r++) {
                const int m = bm + wm + mt * 16 + gid + ((r >= 2) ? 8 : 0);
                const int l = blb + wn + nt * 8 + tig * 2 + (r & 1);
                const float v = acc[mt][nt][r];
                if (MODE == 0) {
                    const int bi = m / Nn, ni = m - bi * Nn;
                    const int sI = l / Cc, rem = l - sI * Cc;
                    const int h = rem >> 6, d = rem & 63;
                    const int bh = bi * Hh + h;
                    if (sI == 0) {
                        split_store(g_qh, g_ql, ((size_t)bh * Nn + ni) * HDm + d, v * QK_SCALE);
                    } else if (sI == 1) {
                        split_store(g_kh, g_kl, ((size_t)bh * Nn + ni) * HDm + d, v);
                    } else {
                        split_store(g_vth, g_vtl, ((size_t)bh * HDm + d) * Nn + ni, v);
                    }
                } else {
                    out[(size_t)m * Cc + l] = v + bias[l];
                }
            }
        }
    }
}

// ---------------------------------------------------------------------------
// scores: per (b,h): S[m,n] = q[m,:]·k[n,:]. CTA 192(m)x64(n), K=64 one-shot.
// 384 thr = 12 warps (6m x 2n), warp 32x32. Dynamic smem (73728 B).
// ---------------------------------------------------------------------------
#define SC_SMEM (size_t)((2 * 192 * 72 + 2 * 64 * 72) * 2)

__global__ void __launch_bounds__(384) k_scores() {
    extern __shared__ __nv_bfloat16 smsc[];
    __nv_bfloat16* sQh = smsc;                    // [192][72]
    __nv_bfloat16* sQl = sQh + 192 * 72;
    __nv_bfloat16* sKh = sQl + 192 * 72;          // [64][72]
    __nv_bfloat16* sKl = sKh + 64 * 72;

    const int bh = blockIdx.z;
    const int bm = blockIdx.y * 192, bn = blockIdx.x * 64;
    const int t = threadIdx.x, lane = t & 31, warp = t >> 5;
    const int gid = lane >> 2, tig = lane & 3;
    const int wm = (warp >> 1) * 32, wn = (warp & 1) * 32;

    {
        const int row = t >> 1, cb = (t & 1) * 32;
#pragma unroll
        for (int j = 0; j < 4; j++) {
            const int col = cb + j * 8;
            *(uint4*)&sQh[row * 72 + col] = *(const uint4*)&g_qh[((size_t)bh * Nn + bm + row) * HDm + col];
            *(uint4*)&sQl[row * 72 + col] = *(const uint4*)&g_ql[((size_t)bh * Nn + bm + row) * HDm + col];
        }
        if (t < 128) {
#pragma unroll
            for (int j = 0; j < 4; j++) {
                const int col = cb + j * 8;
                *(uint4*)&sKh[row * 72 + col] = *(const uint4*)&g_kh[((size_t)bh * Nn + bn + row) * HDm + col];
                *(uint4*)&sKl[row * 72 + col] = *(const uint4*)&g_kl[((size_t)bh * Nn + bn + row) * HDm + col];
            }
        }
    }
    __syncthreads();

    float acc[2][4][4];
#pragma unroll
    for (int mt = 0; mt < 2; mt++)
#pragma unroll
        for (int nt = 0; nt < 4; nt++)
#pragma unroll
            for (int r = 0; r < 4; r++) acc[mt][nt][r] = 0.f;

#pragma unroll
    for (int kk = 0; kk < 64; kk += 16) {
        uint32_t ah[2][4], al[2][4];
#pragma unroll
        for (int mt = 0; mt < 2; mt++) {
            const int r0 = wm + mt * 16 + gid;
            ah[mt][0] = *(const uint32_t*)&sQh[r0 * 72 + kk + tig * 2];
            ah[mt][1] = *(const uint32_t*)&sQh[(r0 + 8) * 72 + kk + tig * 2];
            ah[mt][2] = *(const uint32_t*)&sQh[r0 * 72 + kk + tig * 2 + 8];
            ah[mt][3] = *(const uint32_t*)&sQh[(r0 + 8) * 72 + kk + tig * 2 + 8];
            al[mt][0] = *(const uint32_t*)&sQl[r0 * 72 + kk + tig * 2];
            al[mt][1] = *(const uint32_t*)&sQl[(r0 + 8) * 72 + kk + tig * 2];
            al[mt][2] = *(const uint32_t*)&sQl[r0 * 72 + kk + tig * 2 + 8];
            al[mt][3] = *(const uint32_t*)&sQl[(r0 + 8) * 72 + kk + tig * 2 + 8];
        }
        uint32_t bh2[4][2], bl2[4][2];
#pragma unroll
        for (int nt = 0; nt < 4; nt++) {
            const int c0 = wn + nt * 8 + gid;
            bh2[nt][0] = *(const uint32_t*)&sKh[c0 * 72 + kk + tig * 2];
            bh2[nt][1] = *(const uint32_t*)&sKh[c0 * 72 + kk + tig * 2 + 8];
            bl2[nt][0] = *(const uint32_t*)&sKl[c0 * 72 + kk + tig * 2];
            bl2[nt][1] = *(const uint32_t*)&sKl[c0 * 72 + kk + tig * 2 + 8];
        }
#pragma unroll
        for (int mt = 0; mt < 2; mt++)
#pragma unroll
            for (int nt = 0; nt < 4; nt++) {
                MMA_BF16(acc[mt][nt], ah[mt], bh2[nt]);
                MMA_BF16(acc[mt][nt], ah[mt], bl2[nt]);
                MMA_BF16(acc[mt][nt], al[mt], bh2[nt]);
            }
    }

#pragma unroll
    for (int mt = 0; mt < 2; mt++)
#pragma unroll
        for (int nt = 0; nt < 4; nt++)
#pragma unroll
            for (int rp = 0; rp < 2; rp++) {
                const int m = bm + wm + mt * 16 + gid + rp * 8;
                const int n = bn + wn + nt * 8 + tig * 2;
                float2 v = make_float2(acc[mt][nt][rp * 2], acc[mt][nt][rp * 2 + 1]);
                *(float2*)&g_s[((size_t)bh * Nn + m) * Nn + n] = v;
            }
}

// ---------------------------------------------------------------------------
// fused talking-heads mix + softmax + mix; writes P2 as bf16 split
// ---------------------------------------------------------------------------
__global__ void __launch_bounds__(576) k_mix_softmax(const float* __restrict__ Wl,
                                                     const float* __restrict__ bl,
                                                     const float* __restrict__ Ww,
                                                     const float* __restrict__ bw) {
    const int bm = blockIdx.x;
    const int b = bm / Nn, m = bm - b * Nn;
    const int n = threadIdx.x;
    const int lane = threadIdx.x & 31, wp = threadIdx.x >> 5;

    __shared__ float sWl[144], sWw[144], sbl[12], sbw[12];
    __shared__ float red[12][20];
    __shared__ float rowstat[12];

    if (threadIdx.x < 144) { sWl[threadIdx.x] = Wl[threadIdx.x]; sWw[threadIdx.x] = Ww[threadIdx.x]; }
    if (threadIdx.x < 12)  { sbl[threadIdx.x] = bl[threadIdx.x]; sbw[threadIdx.x] = bw[threadIdx.x]; }
    __syncthreads();

    const size_t base = ((size_t)(b * Hh) * Nn + m) * Nn + n;
    const size_t hstr = (size_t)Nn * Nn;

    float s[12];
#pragma unroll
    for (int h = 0; h < 12; h++) s[h] = g_s[base + (size_t)h * hstr];

    float a[12];
#pragma unroll
    for (int g = 0; g < 12; g++) {
        float acc = sbl[g];
#pragma unroll
        for (int h = 0; h < 12; h++) acc = fmaf(sWl[g * 12 + h], s[h], acc);
        a[g] = acc;
    }

#pragma unroll
    for (int g = 0; g < 12; g++) {
        float v = a[g];
#pragma unroll
        for (int o = 16; o > 0; o >>= 1) v = fmaxf(v, __shfl_xor_sync(0xffffffffu, v, o));
        if (lane == 0) red[g][wp] = v;
    }
    __syncthreads();
    if (threadIdx.x < 12) {
        float v = red[threadIdx.x][0];
        for (int w2 = 1; w2 < 18; w2++) v = fmaxf(v, red[threadIdx.x][w2]);
        rowstat[threadIdx.x] = v;
    }
    __syncthreads();

    float p[12];
#pragma unroll
    for (int g = 0; g < 12; g++) p[g] = __expf(a[g] - rowstat[g]);
    __syncthreads();

#pragma unroll
    for (int g = 0; g < 12; g++) {
        float v = p[g];
#pragma unroll
        for (int o = 16; o > 0; o >>= 1) v += __shfl_xor_sync(0xffffffffu, v, o);
        if (lane == 0) red[g][wp] = v;
    }
    __syncthreads();
    if (threadIdx.x < 12) {
        float v = 0.f;
        for (int w2 = 0; w2 < 18; w2++) v += red[threadIdx.x][w2];
        rowstat[threadIdx.x] = 1.0f / v;
    }
    __syncthreads();

#pragma unroll
    for (int g = 0; g < 12; g++) p[g] *= rowstat[g];

#pragma unroll
    for (int g = 0; g < 12; g++) {
        float acc = sbw[g];
#pragma unroll
        for (int h = 0; h < 12; h++) acc = fmaf(sWw[g * 12 + h], p[h], acc);
        split_store(g_p2h, g_p2l, base + (size_t)g * hstr, acc);
    }
}

// ---------------------------------------------------------------------------
// PV: per (b,h): O[m,d] = sum_n P2[m,n] Vt[d,n]. CTA 192(m)x64(d), K=576,
// BK=32, 3-stage cp.async, 384 thr = 12 warps (6m x 2d), warp 32x32.
// dyn smem: Ph[3][192][40], Pl, Vh[3][64][40], Vl = 122880 B
// ---------------------------------------------------------------------------
#define PV_SMEM (size_t)((3 * 192 * 40 * 2 + 3 * 64 * 40 * 2) * 2)

__global__ void __launch_bounds__(384, 1) k_pv() {
    extern __shared__ __nv_bfloat16 smpv[];
    __nv_bfloat16* sPh = smpv;                    // 3 stages of [192][40]
    __nv_bfloat16* sPl = sPh + 3 * 192 * 40;
    __nv_bfloat16* sVh = sPl + 3 * 192 * 40;      // 3 stages of [64][40]
    __nv_bfloat16* sVl = sVh + 3 * 64 * 40;

    const int bh = blockIdx.y;
    const int bm = blockIdx.x * 192;
    const int t = threadIdx.x, lane = t & 31, warp = t >> 5;
    const int gid = lane >> 2, tig = lane & 3;
    const int wm = (warp >> 1) * 32, wn = (warp & 1) * 32;

    const int prow = t >> 1, pcol = (t & 1) * 16;  // P loads: 192 rows x {0,16}
    const __nv_bfloat16* gPh = g_p2h + ((size_t)bh * Nn + bm + prow) * Nn + pcol;
    const __nv_bfloat16* gPl = g_p2l + ((size_t)bh * Nn + bm + prow) * Nn + pcol;
    // V pointers only meaningful for t < 128 (rows 0..63 of Vt)
    const int vrow = (t < 128) ? prow : 0;
    const __nv_bfloat16* gVh = g_vth + ((size_t)bh * HDm + vrow) * Nn + pcol;
    const __nv_bfloat16* gVl = g_vtl + ((size_t)bh * HDm + vrow) * Nn + pcol;

    const uint32_t dPh = smem_u32(sPh) + (uint32_t)(prow * 40 + pcol) * 2;
    const uint32_t dPl = smem_u32(sPl) + (uint32_t)(prow * 40 + pcol) * 2;
    const uint32_t dVh = smem_u32(sVh) + (uint32_t)(vrow * 40 + pcol) * 2;
    const uint32_t dVl = smem_u32(sVl) + (uint32_t)(vrow * 40 + pcol) * 2;
    const uint32_t stP = 192 * 40 * 2, stV = 64 * 40 * 2;

    auto issue = [&](int s, int kt) {
        const int k0 = kt * 32;
        cp16(dPh + s * stP,      gPh + k0);
        cp16(dPh + s * stP + 16, gPh + k0 + 8);
        cp16(dPl + s * stP,      gPl + k0);
        cp16(dPl + s * stP + 16, gPl + k0 + 8);
        if (t < 128) {
            cp16(dVh + s * stV,      gVh + k0);
            cp16(dVh + s * stV + 16, gVh + k0 + 8);
            cp16(dVl + s * stV,      gVl + k0);
            cp16(dVl + s * stV + 16, gVl + k0 + 8);
        }
        CP_COMMIT();
    };

    float acc[2][4][4];
#pragma unroll
    for (int mt = 0; mt < 2; mt++)
#pragma unroll
        for (int nt = 0; nt < 4; nt++)
#pragma unroll
            for (int r = 0; r < 4; r++) acc[mt][nt][r] = 0.f;

    const int KT = Nn / 32;   // 18
    issue(0, 0);
    issue(1, 1);

    for (int kt = 0; kt < KT; kt++) {
        const int st = kt % 3;
        if (kt + 1 < KT) { CP_WAIT(1); } else { CP_WAIT(0); }
        __syncthreads();
        if (kt + 2 < KT) issue((kt + 2) % 3, kt + 2);

        const __nv_bfloat16* pPh = sPh + st * 192 * 40;
        const __nv_bfloat16* pPl = sPl + st * 192 * 40;
        const __nv_bfloat16* pVh = sVh + st * 64 * 40;
        const __nv_bfloat16* pVl = sVl + st * 64 * 40;
#pragma unroll
        for (int kk = 0; kk < 32; kk += 16) {
            uint32_t ah[2][4], al[2][4];
#pragma unroll
            for (int mt = 0; mt < 2; mt++) {
                const int r0 = wm + mt * 16 + gid;
                ah[mt][0] = *(const uint32_t*)&pPh[r0 * 40 + kk + tig * 2];
                ah[mt][1] = *(const uint32_t*)&pPh[(r0 + 8) * 40 + kk + tig * 2];
                ah[mt][2] = *(const uint32_t*)&pPh[r0 * 40 + kk + tig * 2 + 8];
                ah[mt][3] = *(const uint32_t*)&pPh[(r0 + 8) * 40 + kk + tig * 2 + 8];
                al[mt][0] = *(const uint32_t*)&pPl[r0 * 40 + kk + tig * 2];
                al[mt][1] = *(const uint32_t*)&pPl[(r0 + 8) * 40 + kk + tig * 2];
                al[mt][2] = *(const uint32_t*)&pPl[r0 * 40 + kk + tig * 2 + 8];
                al[mt][3] = *(const uint32_t*)&pPl[(r0 + 8) * 40 + kk + tig * 2 + 8];
            }
            uint32_t bh2[4][2], bl2[4][2];
#pragma unroll
            for (int nt = 0; nt < 4; nt++) {
                const int c0 = wn + nt * 8 + gid;
                bh2[nt][0] = *(const uint32_t*)&pVh[c0 * 40 + kk + tig * 2];
                bh2[nt][1] = *(const uint32_t*)&pVh[c0 * 40 + kk + tig * 2 + 8];
                bl2[nt][0] = *(const uint32_t*)&pVl[c0 * 40 + kk + tig * 2];
                bl2[nt][1] = *(const uint32_t*)&pVl[c0 * 40 + kk + tig * 2 + 8];
            }
#pragma unroll
            for (int mt = 0; mt < 2; mt++)
#pragma unroll
                for (int nt = 0; nt < 4; nt++) {
                    MMA_BF16(acc[mt][nt], ah[mt], bh2[nt]);
                    MMA_BF16(acc[mt][nt], ah[mt], bl2[nt]);
                    MMA_BF16(acc[mt][nt], al[mt], bh2[nt]);
                }
        }
    }

    const int b = bh / Hh, h = bh - b * Hh;
#pragma unroll
    for (int mt = 0; mt < 2; mt++)
#pragma unroll
        for (int nt = 0; nt < 4; nt++)
#pragma unroll
            for (int rp = 0; rp < 2; rp++) {
                const int m = bm + wm + mt * 16 + gid + rp * 8;
                const int d = wn + nt * 8 + tig * 2;
                const size_t idx = ((size_t)(b * Nn + m)) * Cc + h * HDm + d;
                const float v0 = acc[mt][nt][rp * 2];
                const float v1 = acc[mt][nt][rp * 2 + 1];
                __nv_bfloat16 h0 = __float2bfloat16_rn(v0);
                __nv_bfloat16 h1 = __float2bfloat16_rn(v1);
                __nv_bfloat162 hp; hp.x = h0; hp.y = h1;
                __nv_bfloat162 lp;
                lp.x = __float2bfloat16_rn(v0 - __bfloat162float(h0));
                lp.y = __float2bfloat16_rn(v1 - __bfloat162float(h1));
                *(__nv_bfloat162*)&g_ohh[idx] = hp;
                *(__nv_bfloat162*)&g_ohl[idx] = lp;
            }
}

// ---------------------------------------------------------------------------
extern "C" void kernel_launch(void* const* d_in, const int* in_sizes, int n_in,
                              void* d_out, int out_size) {
    const float* x     = (const float*)d_in[0];
    const float* Wqkv  = (const float*)d_in[1];
    const float* Wl    = (const float*)d_in[2];
    const float* bl    = (const float*)d_in[3];
    const float* Ww    = (const float*)d_in[4];
    const float* bw    = (const float*)d_in[5];
    const float* Wproj = (const float*)d_in[6];
    const float* bproj = (const float*)d_in[7];
    float* out = (float*)d_out;

    __nv_bfloat16 *xh, *xl, *wqh, *wql, *wph, *wpl, *ohh, *ohl;
    cudaGetSymbolAddress((void**)&xh,  g_xh);  cudaGetSymbolAddress((void**)&xl,  g_xl);
    cudaGetSymbolAddress((void**)&wqh, g_wqh); cudaGetSymbolAddress((void**)&wql, g_wql);
    cudaGetSymbolAddress((void**)&wph, g_wph); cudaGetSymbolAddress((void**)&wpl, g_wpl);
    cudaGetSymbolAddress((void**)&ohh, g_ohh); cudaGetSymbolAddress((void**)&ohl, g_ohl);

    cudaFuncSetAttribute(k_gemm<0>, cudaFuncAttributeMaxDynamicSharedMemorySize, (int)GEMM_SMEM);
    cudaFuncSetAttribute(k_gemm<1>, cudaFuncAttributeMaxDynamicSharedMemorySize, (int)GEMM_SMEM);
    cudaFuncSetAttribute(k_scores,  cudaFuncAttributeMaxDynamicSharedMemorySize, (int)SC_SMEM);
    cudaFuncSetAttribute(k_pv,      cudaFuncAttributeMaxDynamicSharedMemorySize, (int)PV_SMEM);

    const int nX  = BN * Cc;
    const int nWq = C3 * Cc;
    const int nWp = Cc * Cc;
    k_split<<<(nX  + 255) / 256, 256>>>(x,     xh,  xl,  nX);
    k_split<<<(nWq + 255) / 256, 256>>>(Wqkv,  wqh, wql, nWq);
    k_split<<<(nWp + 255) / 256, 256>>>(Wproj, wph, wpl, nWp);

    k_gemm<0><<<dim3(C3 / 64, BN / 128), 256, GEMM_SMEM>>>(xh, xl, wqh, wql, nullptr, nullptr);
    k_scores<<<dim3(Nn / 64, Nn / 192, BH), 384, SC_SMEM>>>();
    k_mix_softmax<<<BN, 576>>>(Wl, bl, Ww, bw);
    k_pv<<<dim3(Nn / 192, BH), 384, PV_SMEM>>>();
    k_gemm<1><<<dim3(Cc / 64, BN / 128), 256, GEMM_SMEM>>>(ohh, ohl, wph, wpl, bproj, out);
}

// round 8
// speedup vs baseline: 1.8511x; 1.0021x over previous
#include <cuda_runtime.h>
#include <cuda_bf16.h>
#include <cstdint>

// ---------------------------------------------------------------------------
// TalkingHeadAttn (B=16, N=576, C=768, H=12, HD=64)
// R8 (resubmit of R7; broker container failed before execution, twice seen
//     previously in R0/R5 and resolved by unchanged resubmission):
//     ONE change vs the 1104us R6 baseline: 3-term split MMAs reordered
//     term-major (all hh, then all hl, then all lh) so consecutive MMAs on
//     the same accumulator are 8 apart instead of back-to-back (RAW chain).
// ---------------------------------------------------------------------------

#define Bb 16
#define Nn 576
#define Cc 768
#define Hh 12
#define HDm 64
#define BN (Bb * Nn)     // 9216
#define C3 (3 * Cc)      // 2304
#define BH (Bb * Hh)     // 192
#define QK_SCALE 0.125f

// ---- scratch -----------------------------------------------------------
__device__ float g_s[(size_t)BH * Nn * Nn];                        // 255 MB
__device__ __nv_bfloat16 g_qh[(size_t)BH * Nn * HDm], g_ql[(size_t)BH * Nn * HDm];
__device__ __nv_bfloat16 g_kh[(size_t)BH * Nn * HDm], g_kl[(size_t)BH * Nn * HDm];
__device__ __nv_bfloat16 g_vth[(size_t)BH * HDm * Nn], g_vtl[(size_t)BH * HDm * Nn];
__device__ __nv_bfloat16 g_p2h[(size_t)BH * Nn * Nn], g_p2l[(size_t)BH * Nn * Nn];
__device__ __nv_bfloat16 g_ohh[(size_t)BN * Cc], g_ohl[(size_t)BN * Cc];
__device__ __nv_bfloat16 g_xh[(size_t)BN * Cc],  g_xl[(size_t)BN * Cc];
__device__ __nv_bfloat16 g_wqh[(size_t)C3 * Cc], g_wql[(size_t)C3 * Cc];
__device__ __nv_bfloat16 g_wph[(size_t)Cc * Cc], g_wpl[(size_t)Cc * Cc];

// ---- helpers -----------------------------------------------------------
#define MMA_BF16(C, A, B)                                                     \
    asm volatile(                                                             \
        "mma.sync.aligned.m16n8k16.row.col.f32.bf16.bf16.f32 "                \
        "{%0,%1,%2,%3}, {%4,%5,%6,%7}, {%8,%9}, {%0,%1,%2,%3};\n"             \
        : "+f"((C)[0]), "+f"((C)[1]), "+f"((C)[2]), "+f"((C)[3])              \
        : "r"((A)[0]), "r"((A)[1]), "r"((A)[2]), "r"((A)[3]),                 \
          "r"((B)[0]), "r"((B)[1]))

__device__ __forceinline__ uint32_t smem_u32(const void* p) {
    return static_cast<uint32_t>(__cvta_generic_to_shared(p));
}
__device__ __forceinline__ void cp16(uint32_t dst, const void* src) {
    asm volatile("cp.async.cg.shared.global [%0], [%1], 16;\n" :: "r"(dst), "l"(src));
}
#define CP_COMMIT() asm volatile("cp.async.commit_group;\n")
#define CP_WAIT(n)  asm volatile("cp.async.wait_group %0;\n" :: "n"(n))

__device__ __forceinline__ void split_store(__nv_bfloat16* hi, __nv_bfloat16* lo,
                                            size_t idx, float v) {
    __nv_bfloat16 h = __float2bfloat16_rn(v);
    hi[idx] = h;
    lo[idx] = __float2bfloat16_rn(v - __bfloat162float(h));
}

// ---------------------------------------------------------------------------
__global__ void k_split(const float* __restrict__ src,
                        __nv_bfloat16* __restrict__ hi,
                        __nv_bfloat16* __restrict__ lo, int n) {
    int i = blockIdx.x * blockDim.x + threadIdx.x;
    if (i < n) {
        float x = src[i];
        __nv_bfloat16 h = __float2bfloat16_rn(x);
        hi[i] = h;
        lo[i] = __float2bfloat16_rn(x - __bfloat162float(h));
    }
}

// ---------------------------------------------------------------------------
// GEMM C[m,l] = sum_k A[m,k]*W[l,k], K=768. CTA 128x64, BK=32, 3-stage cp.async.
// 256 thr, 8 warps (4m x 2n), warp tile 32x32. MODE0: qkv scatter; MODE1: proj.
// ---------------------------------------------------------------------------
#define GEMM_SMEM (size_t)((3 * 128 * 40 + 3 * 128 * 40 + 3 * 64 * 40 + 3 * 64 * 40) * 2)

template <int MODE>
__global__ void __launch_bounds__(256, 2) k_gemm(
    const __nv_bfloat16* __restrict__ Ah_, const __nv_bfloat16* __restrict__ Al_,
    const __nv_bfloat16* __restrict__ Wh_, const __nv_bfloat16* __restrict__ Wl_,
    const float* __restrict__ bias, float* __restrict__ out) {

    extern __shared__ __nv_bfloat16 smem[];
    __nv_bfloat16* sAh = smem;
    __nv_bfloat16* sAl = sAh + 3 * 128 * 40;
    __nv_bfloat16* sBh = sAl + 3 * 128 * 40;
    __nv_bfloat16* sBl = sBh + 3 * 64 * 40;

    const int bm = blockIdx.y * 128;
    const int blb = blockIdx.x * 64;
    const int t = threadIdx.x, lane = t & 31, warp = t >> 5;
    const int gid = lane >> 2, tig = lane & 3;
    const int wm = (warp >> 1) * 32, wn = (warp & 1) * 32;

    const int arow = t >> 1, acol = (t & 1) * 16;
    const int brow = t >> 2, bcol = (t & 3) * 8;

    const __nv_bfloat16* gAh = Ah_ + (size_t)(bm + arow) * Cc + acol;
    const __nv_bfloat16* gAl = Al_ + (size_t)(bm + arow) * Cc + acol;
    const __nv_bfloat16* gBh = Wh_ + (size_t)(blb + brow) * Cc + bcol;
    const __nv_bfloat16* gBl = Wl_ + (size_t)(blb + brow) * Cc + bcol;

    const uint32_t dAh = smem_u32(sAh) + (uint32_t)(arow * 40 + acol) * 2;
    const uint32_t dAl = smem_u32(sAl) + (uint32_t)(arow * 40 + acol) * 2;
    const uint32_t dBh = smem_u32(sBh) + (uint32_t)(brow * 40 + bcol) * 2;
    const uint32_t dBl = smem_u32(sBl) + (uint32_t)(brow * 40 + bcol) * 2;
    const uint32_t stA = 128 * 40 * 2, stB = 64 * 40 * 2;

    auto issue = [&](int s, int kt) {
        const int k0 = kt * 32;
        cp16(dAh + s * stA,      gAh + k0);
        cp16(dAh + s * stA + 16, gAh + k0 + 8);
        cp16(dAl + s * stA,      gAl + k0);
        cp16(dAl + s * stA + 16, gAl + k0 + 8);
        cp16(dBh + s * stB,      gBh + k0);
        cp16(dBl + s * stB,      gBl + k0);
        CP_COMMIT();
    };

    float acc[2][4][4];
#pragma unroll
    for (int mt = 0; mt < 2; mt++)
#pragma unroll
        for (int nt = 0; nt < 4; nt++)
#pragma unroll
            for (int r = 0; r < 4; r++) acc[mt][nt][r] = 0.f;

    const int KT = Cc / 32;   // 24
    issue(0, 0);
    issue(1, 1);

    for (int kt = 0; kt < KT; kt++) {
        const int st = kt % 3;
        if (kt + 1 < KT) { CP_WAIT(1); } else { CP_WAIT(0); }
        __syncthreads();
        if (kt + 2 < KT) issue((kt + 2) % 3, kt + 2);

        const __nv_bfloat16* pAh = sAh + st * 128 * 40;
        const __nv_bfloat16* pAl = sAl + st * 128 * 40;
        const __nv_bfloat16* pBh = sBh + st * 64 * 40;
        const __nv_bfloat16* pBl = sBl + st * 64 * 40;
#pragma unroll
        for (int kk = 0; kk < 32; kk += 16) {
            uint32_t ah[2][4], al[2][4];
#pragma unroll
            for (int mt = 0; mt < 2; mt++) {
                const int r0 = wm + mt * 16 + gid;
                ah[mt][0] = *(const uint32_t*)&pAh[r0 * 40 + kk + tig * 2];
                ah[mt][1] = *(const uint32_t*)&pAh[(r0 + 8) * 40 + kk + tig * 2];
                ah[mt][2] = *(const uint32_t*)&pAh[r0 * 40 + kk + tig * 2 + 8];
                ah[mt][3] = *(const uint32_t*)&pAh[(r0 + 8) * 40 + kk + tig * 2 + 8];
                al[mt][0] = *(const uint32_t*)&pAl[r0 * 40 + kk + tig * 2];
                al[mt][1] = *(const uint32_t*)&pAl[(r0 + 8) * 40 + kk + tig * 2];
                al[mt][2] = *(const uint32_t*)&pAl[r0 * 40 + kk + tig * 2 + 8];
                al[mt][3] = *(const uint32_t*)&pAl[(r0 + 8) * 40 + kk + tig * 2 + 8];
            }
            uint32_t bh2[4][2], bl2[4][2];
#pragma unroll
            for (int nt = 0; nt < 4; nt++) {
                const int c0 = wn + nt * 8 + gid;
                bh2[nt][0] = *(const uint32_t*)&pBh[c0 * 40 + kk + tig * 2];
                bh2[nt][1] = *(const uint32_t*)&pBh[c0 * 40 + kk + tig * 2 + 8];
                bl2[nt][0] = *(const uint32_t*)&pBl[c0 * 40 + kk + tig * 2];
                bl2[nt][1] = *(const uint32_t*)&pBl[c0 * 40 + kk + tig * 2 + 8];
            }
            // term-major order: same-accumulator MMAs are 8 apart
#pragma unroll
            for (int mt = 0; mt < 2; mt++)
#pragma unroll
                for (int nt = 0; nt < 4; nt++)
                    MMA_BF16(acc[mt][nt], ah[mt], bh2[nt]);
#pragma unroll
            for (int mt = 0; mt < 2; mt++)
#pragma unroll
                for (int nt = 0; nt < 4; nt++)
                    MMA_BF16(acc[mt][nt], ah[mt], bl2[nt]);
#pragma unroll
            for (int mt = 0; mt < 2; mt++)
#pragma unroll
                for (int nt = 0; nt < 4; nt++)
                    MMA_BF16(acc[mt][nt], al[mt], bh2[nt]);
        }
    }

#pragma unroll
    for (int mt = 0; mt < 2; mt++) {
#pragma unroll
        for (int nt = 0; nt < 4; nt++) {
#pragma unroll
            for (int r = 0; r < 4; r++) {
                const int m = bm + wm + mt * 16 + gid + ((r >= 2) ? 8 : 0);
                const int l = blb + wn + nt * 8 + tig * 2 + (r & 1);
                const float v = acc[mt][nt][r];
                if (MODE == 0) {
                    const int bi = m / Nn, ni = m - bi * Nn;
                    const int sI = l / Cc, rem = l - sI * Cc;
                    const int h = rem >> 6, d = rem & 63;
                    const int bh = bi * Hh + h;
                    if (sI == 0) {
                        split_store(g_qh, g_ql, ((size_t)bh * Nn + ni) * HDm + d, v * QK_SCALE);
                    } else if (sI == 1) {
                        split_store(g_kh, g_kl, ((size_t)bh * Nn + ni) * HDm + d, v);
                    } else {
                        split_store(g_vth, g_vtl, ((size_t)bh * HDm + d) * Nn + ni, v);
                    }
                } else {
                    out[(size_t)m * Cc + l] = v + bias[l];
                }
            }
        }
    }
}

// ---------------------------------------------------------------------------
// scores: per (b,h): S[m,n] = q[m,:]·k[n,:]. CTA 192(m)x64(n), K=64 one-shot.
// 384 thr = 12 warps (6m x 2n), warp 32x32. Dynamic smem (73728 B).
// ---------------------------------------------------------------------------
#define SC_SMEM (size_t)((2 * 192 * 72 + 2 * 64 * 72) * 2)

__global__ void __launch_bounds__(384) k_scores() {
    extern __shared__ __nv_bfloat16 smsc[];
    __nv_bfloat16* sQh = smsc;                    // [192][72]
    __nv_bfloat16* sQl = sQh + 192 * 72;
    __nv_bfloat16* sKh = sQl + 192 * 72;          // [64][72]
    __nv_bfloat16* sKl = sKh + 64 * 72;

    const int bh = blockIdx.z;
    const int bm = blockIdx.y * 192, bn = blockIdx.x * 64;
    const int t = threadIdx.x, lane = t & 31, warp = t >> 5;
    const int gid = lane >> 2, tig = lane & 3;
    const int wm = (warp >> 1) * 32, wn = (warp & 1) * 32;

    {
        const int row = t >> 1, cb = (t & 1) * 32;
#pragma unroll
        for (int j = 0; j < 4; j++) {
            const int col = cb + j * 8;
            *(uint4*)&sQh[row * 72 + col] = *(const uint4*)&g_qh[((size_t)bh * Nn + bm + row) * HDm + col];
            *(uint4*)&sQl[row * 72 + col] = *(const uint4*)&g_ql[((size_t)bh * Nn + bm + row) * HDm + col];
        }
        if (t < 128) {
#pragma unroll
            for (int j = 0; j < 4; j++) {
                const int col = cb + j * 8;
                *(uint4*)&sKh[row * 72 + col] = *(const uint4*)&g_kh[((size_t)bh * Nn + bn + row) * HDm + col];
                *(uint4*)&sKl[row * 72 + col] = *(const uint4*)&g_kl[((size_t)bh * Nn + bn + row) * HDm + col];
            }
        }
    }
    __syncthreads();

    float acc[2][4][4];
#pragma unroll
    for (int mt = 0; mt < 2; mt++)
#pragma unroll
        for (int nt = 0; nt < 4; nt++)
#pragma unroll
            for (int r = 0; r < 4; r++) acc[mt][nt][r] = 0.f;

#pragma unroll
    for (int kk = 0; kk < 64; kk += 16) {
        uint32_t ah[2][4], al[2][4];
#pragma unroll
        for (int mt = 0; mt < 2; mt++) {
            const int r0 = wm + mt * 16 + gid;
            ah[mt][0] = *(const uint32_t*)&sQh[r0 * 72 + kk + tig * 2];
            ah[mt][1] = *(const uint32_t*)&sQh[(r0 + 8) * 72 + kk + tig * 2];
            ah[mt][2] = *(const uint32_t*)&sQh[r0 * 72 + kk + tig * 2 + 8];
            ah[mt][3] = *(const uint32_t*)&sQh[(r0 + 8) * 72 + kk + tig * 2 + 8];
            al[mt][0] = *(const uint32_t*)&sQl[r0 * 72 + kk + tig * 2];
            al[mt][1] = *(const uint32_t*)&sQl[(r0 + 8) * 72 + kk + tig * 2];
            al[mt][2] = *(const uint32_t*)&sQl[r0 * 72 + kk + tig * 2 + 8];
            al[mt][3] = *(const uint32_t*)&sQl[(r0 + 8) * 72 + kk + tig * 2 + 8];
        }
        uint32_t bh2[4][2], bl2[4][2];
#pragma unroll
        for (int nt = 0; nt < 4; nt++) {
            const int c0 = wn + nt * 8 + gid;
            bh2[nt][0] = *(const uint32_t*)&sKh[c0 * 72 + kk + tig * 2];
            bh2[nt][1] = *(const uint32_t*)&sKh[c0 * 72 + kk + tig * 2 + 8];
            bl2[nt][0] = *(const uint32_t*)&sKl[c0 * 72 + kk + tig * 2];
            bl2[nt][1] = *(const uint32_t*)&sKl[c0 * 72 + kk + tig * 2 + 8];
        }
        // term-major order
#pragma unroll
        for (int mt = 0; mt < 2; mt++)
#pragma unroll
            for (int nt = 0; nt < 4; nt++)
                MMA_BF16(acc[mt][nt], ah[mt], bh2[nt]);
#pragma unroll
        for (int mt = 0; mt < 2; mt++)
#pragma unroll
            for (int nt = 0; nt < 4; nt++)
                MMA_BF16(acc[mt][nt], ah[mt], bl2[nt]);
#pragma unroll
        for (int mt = 0; mt < 2; mt++)
#pragma unroll
            for (int nt = 0; nt < 4; nt++)
                MMA_BF16(acc[mt][nt], al[mt], bh2[nt]);
    }

#pragma unroll
    for (int mt = 0; mt < 2; mt++)
#pragma unroll
        for (int nt = 0; nt < 4; nt++)
#pragma unroll
            for (int rp = 0; rp < 2; rp++) {
                const int m = bm + wm + mt * 16 + gid + rp * 8;
                const int n = bn + wn + nt * 8 + tig * 2;
                float2 v = make_float2(acc[mt][nt][rp * 2], acc[mt][nt][rp * 2 + 1]);
                *(float2*)&g_s[((size_t)bh * Nn + m) * Nn + n] = v;
            }
}

// ---------------------------------------------------------------------------
// fused talking-heads mix + softmax + mix; writes P2 as bf16 split
// ---------------------------------------------------------------------------
__global__ void __launch_bounds__(576) k_mix_softmax(const float* __restrict__ Wl,
                                                     const float* __restrict__ bl,
                                                     const float* __restrict__ Ww,
                                                     const float* __restrict__ bw) {
    const int bm = blockIdx.x;
    const int b = bm / Nn, m = bm - b * Nn;
    const int n = threadIdx.x;
    const int lane = threadIdx.x & 31, wp = threadIdx.x >> 5;

    __shared__ float sWl[144], sWw[144], sbl[12], sbw[12];
    __shared__ float red[12][20];
    __shared__ float rowstat[12];

    if (threadIdx.x < 144) { sWl[threadIdx.x] = Wl[threadIdx.x]; sWw[threadIdx.x] = Ww[threadIdx.x]; }
    if (threadIdx.x < 12)  { sbl[threadIdx.x] = bl[threadIdx.x]; sbw[threadIdx.x] = bw[threadIdx.x]; }
    __syncthreads();

    const size_t base = ((size_t)(b * Hh) * Nn + m) * Nn + n;
    const size_t hstr = (size_t)Nn * Nn;

    float s[12];
#pragma unroll
    for (int h = 0; h < 12; h++) s[h] = g_s[base + (size_t)h * hstr];

    float a[12];
#pragma unroll
    for (int g = 0; g < 12; g++) {
        float acc = sbl[g];
#pragma unroll
        for (int h = 0; h < 12; h++) acc = fmaf(sWl[g * 12 + h], s[h], acc);
        a[g] = acc;
    }

#pragma unroll
    for (int g = 0; g < 12; g++) {
        float v = a[g];
#pragma unroll
        for (int o = 16; o > 0; o >>= 1) v = fmaxf(v, __shfl_xor_sync(0xffffffffu, v, o));
        if (lane == 0) red[g][wp] = v;
    }
    __syncthreads();
    if (threadIdx.x < 12) {
        float v = red[threadIdx.x][0];
        for (int w2 = 1; w2 < 18; w2++) v = fmaxf(v, red[threadIdx.x][w2]);
        rowstat[threadIdx.x] = v;
    }
    __syncthreads();

    float p[12];
#pragma unroll
    for (int g = 0; g < 12; g++) p[g] = __expf(a[g] - rowstat[g]);
    __syncthreads();

#pragma unroll
    for (int g = 0; g < 12; g++) {
        float v = p[g];
#pragma unroll
        for (int o = 16; o > 0; o >>= 1) v += __shfl_xor_sync(0xffffffffu, v, o);
        if (lane == 0) red[g][wp] = v;
    }
    __syncthreads();
    if (threadIdx.x < 12) {
        float v = 0.f;
        for (int w2 = 0; w2 < 18; w2++) v += red[threadIdx.x][w2];
        rowstat[threadIdx.x] = 1.0f / v;
    }
    __syncthreads();

#pragma unroll
    for (int g = 0; g < 12; g++) p[g] *= rowstat[g];

#pragma unroll
    for (int g = 0; g < 12; g++) {
        float acc = sbw[g];
#pragma unroll
        for (int h = 0; h < 12; h++) acc = fmaf(sWw[g * 12 + h], p[h], acc);
        split_store(g_p2h, g_p2l, base + (size_t)g * hstr, acc);
    }
}

// ---------------------------------------------------------------------------
// PV: per (b,h): O[m,d] = sum_n P2[m,n] Vt[d,n]. CTA 192(m)x64(d), K=576,
// BK=32, 3-stage cp.async, 384 thr = 12 warps (6m x 2d), warp 32x32.
// ---------------------------------------------------------------------------
#define PV_SMEM (size_t)((3 * 192 * 40 * 2 + 3 * 64 * 40 * 2) * 2)

__global__ void __launch_bounds__(384, 1) k_pv() {
    extern __shared__ __nv_bfloat16 smpv[];
    __nv_bfloat16* sPh = smpv;                    // 3 stages of [192][40]
    __nv_bfloat16* sPl = sPh + 3 * 192 * 40;
    __nv_bfloat16* sVh = sPl + 3 * 192 * 40;      // 3 stages of [64][40]
    __nv_bfloat16* sVl = sVh + 3 * 64 * 40;

    const int bh = blockIdx.y;
    const int bm = blockIdx.x * 192;
    const int t = threadIdx.x, lane = t & 31, warp = t >> 5;
    const int gid = lane >> 2, tig = lane & 3;
    const int wm = (warp >> 1) * 32, wn = (warp & 1) * 32;

    const int prow = t >> 1, pcol = (t & 1) * 16;  // P loads: 192 rows x {0,16}
    const __nv_bfloat16* gPh = g_p2h + ((size_t)bh * Nn + bm + prow) * Nn + pcol;
    const __nv_bfloat16* gPl = g_p2l + ((size_t)bh * Nn + bm + prow) * Nn + pcol;
    const int vrow = (t < 128) ? prow : 0;
    const __nv_bfloat16* gVh = g_vth + ((size_t)bh * HDm + vrow) * Nn + pcol;
    const __nv_bfloat16* gVl = g_vtl + ((size_t)bh * HDm + vrow) * Nn + pcol;

    const uint32_t dPh = smem_u32(sPh) + (uint32_t)(prow * 40 + pcol) * 2;
    const uint32_t dPl = smem_u32(sPl) + (uint32_t)(prow * 40 + pcol) * 2;
    const uint32_t dVh = smem_u32(sVh) + (uint32_t)(vrow * 40 + pcol) * 2;
    const uint32_t dVl = smem_u32(sVl) + (uint32_t)(vrow * 40 + pcol) * 2;
    const uint32_t stP = 192 * 40 * 2, stV = 64 * 40 * 2;

    auto issue = [&](int s, int kt) {
        const int k0 = kt * 32;
        cp16(dPh + s * stP,      gPh + k0);
        cp16(dPh + s * stP + 16, gPh + k0 + 8);
        cp16(dPl + s * stP,      gPl + k0);
        cp16(dPl + s * stP + 16, gPl + k0 + 8);
        if (t < 128) {
            cp16(dVh + s * stV,      gVh + k0);
            cp16(dVh + s * stV + 16, gVh + k0 + 8);
            cp16(dVl + s * stV,      gVl + k0);
            cp16(dVl + s * stV + 16, gVl + k0 + 8);
        }
        CP_COMMIT();
    };

    float acc[2][4][4];
#pragma unroll
    for (int mt = 0; mt < 2; mt++)
#pragma unroll
        for (int nt = 0; nt < 4; nt++)
#pragma unroll
            for (int r = 0; r < 4; r++) acc[mt][nt][r] = 0.f;

    const int KT = Nn / 32;   // 18
    issue(0, 0);
    issue(1, 1);

    for (int kt = 0; kt < KT; kt++) {
        const int st = kt % 3;
        if (kt + 1 < KT) { CP_WAIT(1); } else { CP_WAIT(0); }
        __syncthreads();
        if (kt + 2 < KT) issue((kt + 2) % 3, kt + 2);

        const __nv_bfloat16* pPh = sPh + st * 192 * 40;
        const __nv_bfloat16* pPl = sPl + st * 192 * 40;
        const __nv_bfloat16* pVh = sVh + st * 64 * 40;
        const __nv_bfloat16* pVl = sVl + st * 64 * 40;
#pragma unroll
        for (int kk = 0; kk < 32; kk += 16) {
            uint32_t ah[2][4], al[2][4];
#pragma unroll
            for (int mt = 0; mt < 2; mt++) {
                const int r0 = wm + mt * 16 + gid;
                ah[mt][0] = *(const uint32_t*)&pPh[r0 * 40 + kk + tig * 2];
                ah[mt][1] = *(const uint32_t*)&pPh[(r0 + 8) * 40 + kk + tig * 2];
                ah[mt][2] = *(const uint32_t*)&pPh[r0 * 40 + kk + tig * 2 + 8];
                ah[mt][3] = *(const uint32_t*)&pPh[(r0 + 8) * 40 + kk + tig * 2 + 8];
                al[mt][0] = *(const uint32_t*)&pPl[r0 * 40 + kk + tig * 2];
                al[mt][1] = *(const uint32_t*)&pPl[(r0 + 8) * 40 + kk + tig * 2];
                al[mt][2] = *(const uint32_t*)&pPl[r0 * 40 + kk + tig * 2 + 8];
                al[mt][3] = *(const uint32_t*)&pPl[(r0 + 8) * 40 + kk + tig * 2 + 8];
            }
            uint32_t bh2[4][2], bl2[4][2];
#pragma unroll
            for (int nt = 0; nt < 4; nt++) {
                const int c0 = wn + nt * 8 + gid;
                bh2[nt][0] = *(const uint32_t*)&pVh[c0 * 40 + kk + tig * 2];
                bh2[nt][1] = *(const uint32_t*)&pVh[c0 * 40 + kk + tig * 2 + 8];
                bl2[nt][0] = *(const uint32_t*)&pVl[c0 * 40 + kk + tig * 2];
                bl2[nt][1] = *(const uint32_t*)&pVl[c0 * 40 + kk + tig * 2 + 8];
            }
            // term-major order
#pragma unroll
            for (int mt = 0; mt < 2; mt++)
#pragma unroll
                for (int nt = 0; nt < 4; nt++)
                    MMA_BF16(acc[mt][nt], ah[mt], bh2[nt]);
#pragma unroll
            for (int mt = 0; mt < 2; mt++)
#pragma unroll
                for (int nt = 0; nt < 4; nt++)
                    MMA_BF16(acc[mt][nt], ah[mt], bl2[nt]);
#pragma unroll
            for (int mt = 0; mt < 2; mt++)
#pragma unroll
                for (int nt = 0; nt < 4; nt++)
                    MMA_BF16(acc[mt][nt], al[mt], bh2[nt]);
        }
    }

    const int b = bh / Hh, h = bh - b * Hh;
#pragma unroll
    for (int mt = 0; mt < 2; mt++)
#pragma unroll
        for (int nt = 0; nt < 4; nt++)
#pragma unroll
            for (int rp = 0; rp < 2; rp++) {
                const int m = bm + wm + mt * 16 + gid + rp * 8;
                const int d = wn + nt * 8 + tig * 2;
                const size_t idx = ((size_t)(b * Nn + m)) * Cc + h * HDm + d;
                const float v0 = acc[mt][nt][rp * 2];
                const float v1 = acc[mt][nt][rp * 2 + 1];
                __nv_bfloat16 h0 = __float2bfloat16_rn(v0);
                __nv_bfloat16 h1 = __float2bfloat16_rn(v1);
                __nv_bfloat162 hp; hp.x = h0; hp.y = h1;
                __nv_bfloat162 lp;
                lp.x = __float2bfloat16_rn(v0 - __bfloat162float(h0));
                lp.y = __float2bfloat16_rn(v1 - __bfloat162float(h1));
                *(__nv_bfloat162*)&g_ohh[idx] = hp;
                *(__nv_bfloat162*)&g_ohl[idx] = lp;
            }
}

// ---------------------------------------------------------------------------
extern "C" void kernel_launch(void* const* d_in, const int* in_sizes, int n_in,
                              void* d_out, int out_size) {
    const float* x     = (const float*)d_in[0];
    const float* Wqkv  = (const float*)d_in[1];
    const float* Wl    = (const float*)d_in[2];
    const float* bl    = (const float*)d_in[3];
    const float* Ww    = (const float*)d_in[4];
    const float* bw    = (const float*)d_in[5];
    const float* Wproj = (const float*)d_in[6];
    const float* bproj = (const float*)d_in[7];
    float* out = (float*)d_out;

    __nv_bfloat16 *xh, *xl, *wqh, *wql, *wph, *wpl, *ohh, *ohl;
    cudaGetSymbolAddress((void**)&xh,  g_xh);  cudaGetSymbolAddress((void**)&xl,  g_xl);
    cudaGetSymbolAddress((void**)&wqh, g_wqh); cudaGetSymbolAddress((void**)&wql, g_wql);
    cudaGetSymbolAddress((void**)&wph, g_wph); cudaGetSymbolAddress((void**)&wpl, g_wpl);
    cudaGetSymbolAddress((void**)&ohh, g_ohh); cudaGetSymbolAddress((void**)&ohl, g_ohl);

    cudaFuncSetAttribute(k_gemm<0>, cudaFuncAttributeMaxDynamicSharedMemorySize, (int)GEMM_SMEM);
    cudaFuncSetAttribute(k_gemm<1>, cudaFuncAttributeMaxDynamicSharedMemorySize, (int)GEMM_SMEM);
    cudaFuncSetAttribute(k_scores,  cudaFuncAttributeMaxDynamicSharedMemorySize, (int)SC_SMEM);
    cudaFuncSetAttribute(k_pv,      cudaFuncAttributeMaxDynamicSharedMemorySize, (int)PV_SMEM);

    const int nX  = BN * Cc;
    const int nWq = C3 * Cc;
    const int nWp = Cc * Cc;
    k_split<<<(nX  + 255) / 256, 256>>>(x,     xh,  xl,  nX);
    k_split<<<(nWq + 255) / 256, 256>>>(Wqkv,  wqh, wql, nWq);
    k_split<<<(nWp + 255) / 256, 256>>>(Wproj, wph, wpl, nWp);

    k_gemm<0><<<dim3(C3 / 64, BN / 128), 256, GEMM_SMEM>>>(xh, xl, wqh, wql, nullptr, nullptr);
    k_scores<<<dim3(Nn / 64, Nn / 192, BH), 384, SC_SMEM>>>();
    k_mix_softmax<<<BN, 576>>>(Wl, bl, Ww, bw);
    k_pv<<<dim3(Nn / 192, BH), 384, PV_SMEM>>>();
    k_gemm<1><<<dim3(Cc / 64, BN / 128), 256, GEMM_SMEM>>>(ohh, ohl, wph, wpl, bproj, out);
}

// round 9
// speedup vs baseline: 2.0452x; 1.1048x over previous
#include <cuda_runtime.h>
#include <cuda_bf16.h>
#include <cuda_fp16.h>
#include <cstdint>

// ---------------------------------------------------------------------------
// TalkingHeadAttn (B=16, N=576, C=768, H=12, HD=64)
// R9: legacy mma.sync cap (~216 TF/s) accepted as ground truth (occupancy and
//     instruction-order experiments both null). Reduce MMA count instead:
//     qkv/proj GEMMs -> fp16 2-MMA scheme (A hi+lo fp16, B single fp16,
//     C = Ah*Bh + Al*Bh; dropped-term error ~2^-11/stage, deterministic seed).
//     scores/pv/mix unchanged (bf16 3-term).
// ---------------------------------------------------------------------------

#define Bb 16
#define Nn 576
#define Cc 768
#define Hh 12
#define HDm 64
#define BN (Bb * Nn)     // 9216
#define C3 (3 * Cc)      // 2304
#define BH (Bb * Hh)     // 192
#define QK_SCALE 0.125f

// ---- scratch -----------------------------------------------------------
__device__ float g_s[(size_t)BH * Nn * Nn];                        // 255 MB
__device__ __nv_bfloat16 g_qh[(size_t)BH * Nn * HDm], g_ql[(size_t)BH * Nn * HDm];
__device__ __nv_bfloat16 g_kh[(size_t)BH * Nn * HDm], g_kl[(size_t)BH * Nn * HDm];
__device__ __nv_bfloat16 g_vth[(size_t)BH * HDm * Nn], g_vtl[(size_t)BH * HDm * Nn];
__device__ __nv_bfloat16 g_p2h[(size_t)BH * Nn * Nn], g_p2l[(size_t)BH * Nn * Nn];
// fp16 operands for the weight GEMMs
__device__ __half g_ohh[(size_t)BN * Cc], g_ohl[(size_t)BN * Cc];
__device__ __half g_xh[(size_t)BN * Cc],  g_xl[(size_t)BN * Cc];
__device__ __half g_wqh[(size_t)C3 * Cc];
__device__ __half g_wph[(size_t)Cc * Cc];

// ---- helpers -----------------------------------------------------------
#define MMA_BF16(C, A, B)                                                     \
    asm volatile(                                                             \
        "mma.sync.aligned.m16n8k16.row.col.f32.bf16.bf16.f32 "                \
        "{%0,%1,%2,%3}, {%4,%5,%6,%7}, {%8,%9}, {%0,%1,%2,%3};\n"             \
        : "+f"((C)[0]), "+f"((C)[1]), "+f"((C)[2]), "+f"((C)[3])              \
        : "r"((A)[0]), "r"((A)[1]), "r"((A)[2]), "r"((A)[3]),                 \
          "r"((B)[0]), "r"((B)[1]))

#define MMA_F16(C, A, B)                                                      \
    asm volatile(                                                             \
        "mma.sync.aligned.m16n8k16.row.col.f32.f16.f16.f32 "                  \
        "{%0,%1,%2,%3}, {%4,%5,%6,%7}, {%8,%9}, {%0,%1,%2,%3};\n"             \
        : "+f"((C)[0]), "+f"((C)[1]), "+f"((C)[2]), "+f"((C)[3])              \
        : "r"((A)[0]), "r"((A)[1]), "r"((A)[2]), "r"((A)[3]),                 \
          "r"((B)[0]), "r"((B)[1]))

__device__ __forceinline__ uint32_t smem_u32(const void* p) {
    return static_cast<uint32_t>(__cvta_generic_to_shared(p));
}
__device__ __forceinline__ void cp16(uint32_t dst, const void* src) {
    asm volatile("cp.async.cg.shared.global [%0], [%1], 16;\n" :: "r"(dst), "l"(src));
}
#define CP_COMMIT() asm volatile("cp.async.commit_group;\n")
#define CP_WAIT(n)  asm volatile("cp.async.wait_group %0;\n" :: "n"(n))

__device__ __forceinline__ void split_store(__nv_bfloat16* hi, __nv_bfloat16* lo,
                                            size_t idx, float v) {
    __nv_bfloat16 h = __float2bfloat16_rn(v);
    hi[idx] = h;
    lo[idx] = __float2bfloat16_rn(v - __bfloat162float(h));
}

// ---------------------------------------------------------------------------
__global__ void k_split_pair_h(const float* __restrict__ src,
                               __half* __restrict__ hi,
                               __half* __restrict__ lo, int n) {
    int i = blockIdx.x * blockDim.x + threadIdx.x;
    if (i < n) {
        float x = src[i];
        __half h = __float2half_rn(x);
        hi[i] = h;
        lo[i] = __float2half_rn(x - __half2float(h));
    }
}
__global__ void k_cvt_h(const float* __restrict__ src,
                        __half* __restrict__ dst, int n) {
    int i = blockIdx.x * blockDim.x + threadIdx.x;
    if (i < n) dst[i] = __float2half_rn(src[i]);
}

// ---------------------------------------------------------------------------
// fp16 2-MMA GEMM: C[m,l] = sum_k A[m,k]*W[l,k], K=768. CTA 128x64, BK=32,
// 3-stage cp.async, 256 thr, 8 warps (4m x 2n), warp 32x32.
// smem: Ah[3][128][40], Al[3][128][40], Bh[3][64][40]  (76800 B)
// MODE0: qkv scatter epilogue (bf16 splits). MODE1: proj (+bias).
// ---------------------------------------------------------------------------
#define GEMM_SMEM (size_t)((3 * 128 * 40 + 3 * 128 * 40 + 3 * 64 * 40) * 2)

template <int MODE>
__global__ void __launch_bounds__(256, 2) k_gemm(
    const __half* __restrict__ Ah_, const __half* __restrict__ Al_,
    const __half* __restrict__ Wh_,
    const float* __restrict__ bias, float* __restrict__ out) {

    extern __shared__ __half smem[];
    __half* sAh = smem;
    __half* sAl = sAh + 3 * 128 * 40;
    __half* sBh = sAl + 3 * 128 * 40;

    const int bm = blockIdx.y * 128;
    const int blb = blockIdx.x * 64;
    const int t = threadIdx.x, lane = t & 31, warp = t >> 5;
    const int gid = lane >> 2, tig = lane & 3;
    const int wm = (warp >> 1) * 32, wn = (warp & 1) * 32;

    const int arow = t >> 1, acol = (t & 1) * 16;
    const int brow = t >> 2, bcol = (t & 3) * 8;

    const __half* gAh = Ah_ + (size_t)(bm + arow) * Cc + acol;
    const __half* gAl = Al_ + (size_t)(bm + arow) * Cc + acol;
    const __half* gBh = Wh_ + (size_t)(blb + brow) * Cc + bcol;

    const uint32_t dAh = smem_u32(sAh) + (uint32_t)(arow * 40 + acol) * 2;
    const uint32_t dAl = smem_u32(sAl) + (uint32_t)(arow * 40 + acol) * 2;
    const uint32_t dBh = smem_u32(sBh) + (uint32_t)(brow * 40 + bcol) * 2;
    const uint32_t stA = 128 * 40 * 2, stB = 64 * 40 * 2;

    auto issue = [&](int s, int kt) {
        const int k0 = kt * 32;
        cp16(dAh + s * stA,      gAh + k0);
        cp16(dAh + s * stA + 16, gAh + k0 + 8);
        cp16(dAl + s * stA,      gAl + k0);
        cp16(dAl + s * stA + 16, gAl + k0 + 8);
        cp16(dBh + s * stB,      gBh + k0);
        CP_COMMIT();
    };

    float acc[2][4][4];
#pragma unroll
    for (int mt = 0; mt < 2; mt++)
#pragma unroll
        for (int nt = 0; nt < 4; nt++)
#pragma unroll
            for (int r = 0; r < 4; r++) acc[mt][nt][r] = 0.f;

    const int KT = Cc / 32;   // 24
    issue(0, 0);
    issue(1, 1);

    for (int kt = 0; kt < KT; kt++) {
        const int st = kt % 3;
        if (kt + 1 < KT) { CP_WAIT(1); } else { CP_WAIT(0); }
        __syncthreads();
        if (kt + 2 < KT) issue((kt + 2) % 3, kt + 2);

        const __half* pAh = sAh + st * 128 * 40;
        const __half* pAl = sAl + st * 128 * 40;
        const __half* pBh = sBh + st * 64 * 40;
#pragma unroll
        for (int kk = 0; kk < 32; kk += 16) {
            uint32_t ah[2][4], al[2][4];
#pragma unroll
            for (int mt = 0; mt < 2; mt++) {
                const int r0 = wm + mt * 16 + gid;
                ah[mt][0] = *(const uint32_t*)&pAh[r0 * 40 + kk + tig * 2];
                ah[mt][1] = *(const uint32_t*)&pAh[(r0 + 8) * 40 + kk + tig * 2];
                ah[mt][2] = *(const uint32_t*)&pAh[r0 * 40 + kk + tig * 2 + 8];
                ah[mt][3] = *(const uint32_t*)&pAh[(r0 + 8) * 40 + kk + tig * 2 + 8];
                al[mt][0] = *(const uint32_t*)&pAl[r0 * 40 + kk + tig * 2];
                al[mt][1] = *(const uint32_t*)&pAl[(r0 + 8) * 40 + kk + tig * 2];
                al[mt][2] = *(const uint32_t*)&pAl[r0 * 40 + kk + tig * 2 + 8];
                al[mt][3] = *(const uint32_t*)&pAl[(r0 + 8) * 40 + kk + tig * 2 + 8];
            }
            uint32_t bh2[4][2];
#pragma unroll
            for (int nt = 0; nt < 4; nt++) {
                const int c0 = wn + nt * 8 + gid;
                bh2[nt][0] = *(const uint32_t*)&pBh[c0 * 40 + kk + tig * 2];
                bh2[nt][1] = *(const uint32_t*)&pBh[c0 * 40 + kk + tig * 2 + 8];
            }
#pragma unroll
            for (int mt = 0; mt < 2; mt++)
#pragma unroll
                for (int nt = 0; nt < 4; nt++)
                    MMA_F16(acc[mt][nt], ah[mt], bh2[nt]);
#pragma unroll
            for (int mt = 0; mt < 2; mt++)
#pragma unroll
                for (int nt = 0; nt < 4; nt++)
                    MMA_F16(acc[mt][nt], al[mt], bh2[nt]);
        }
    }

#pragma unroll
    for (int mt = 0; mt < 2; mt++) {
#pragma unroll
        for (int nt = 0; nt < 4; nt++) {
#pragma unroll
            for (int r = 0; r < 4; r++) {
                const int m = bm + wm + mt * 16 + gid + ((r >= 2) ? 8 : 0);
                const int l = blb + wn + nt * 8 + tig * 2 + (r & 1);
                const float v = acc[mt][nt][r];
                if (MODE == 0) {
                    const int bi = m / Nn, ni = m - bi * Nn;
                    const int sI = l / Cc, rem = l - sI * Cc;
                    const int h = rem >> 6, d = rem & 63;
                    const int bh = bi * Hh + h;
                    if (sI == 0) {
                        split_store(g_qh, g_ql, ((size_t)bh * Nn + ni) * HDm + d, v * QK_SCALE);
                    } else if (sI == 1) {
                        split_store(g_kh, g_kl, ((size_t)bh * Nn + ni) * HDm + d, v);
                    } else {
                        split_store(g_vth, g_vtl, ((size_t)bh * HDm + d) * Nn + ni, v);
                    }
                } else {
                    out[(size_t)m * Cc + l] = v + bias[l];
                }
            }
        }
    }
}

// ---------------------------------------------------------------------------
// scores: per (b,h): S[m,n] = q[m,:]·k[n,:]. CTA 192(m)x64(n), K=64 one-shot.
// 384 thr = 12 warps (6m x 2n), warp 32x32. bf16 3-term (unchanged).
// ---------------------------------------------------------------------------
#define SC_SMEM (size_t)((2 * 192 * 72 + 2 * 64 * 72) * 2)

__global__ void __launch_bounds__(384) k_scores() {
    extern __shared__ __nv_bfloat16 smsc[];
    __nv_bfloat16* sQh = smsc;                    // [192][72]
    __nv_bfloat16* sQl = sQh + 192 * 72;
    __nv_bfloat16* sKh = sQl + 192 * 72;          // [64][72]
    __nv_bfloat16* sKl = sKh + 64 * 72;

    const int bh = blockIdx.z;
    const int bm = blockIdx.y * 192, bn = blockIdx.x * 64;
    const int t = threadIdx.x, lane = t & 31, warp = t >> 5;
    const int gid = lane >> 2, tig = lane & 3;
    const int wm = (warp >> 1) * 32, wn = (warp & 1) * 32;

    {
        const int row = t >> 1, cb = (t & 1) * 32;
#pragma unroll
        for (int j = 0; j < 4; j++) {
            const int col = cb + j * 8;
            *(uint4*)&sQh[row * 72 + col] = *(const uint4*)&g_qh[((size_t)bh * Nn + bm + row) * HDm + col];
            *(uint4*)&sQl[row * 72 + col] = *(const uint4*)&g_ql[((size_t)bh * Nn + bm + row) * HDm + col];
        }
        if (t < 128) {
#pragma unroll
            for (int j = 0; j < 4; j++) {
                const int col = cb + j * 8;
                *(uint4*)&sKh[row * 72 + col] = *(const uint4*)&g_kh[((size_t)bh * Nn + bn + row) * HDm + col];
                *(uint4*)&sKl[row * 72 + col] = *(const uint4*)&g_kl[((size_t)bh * Nn + bn + row) * HDm + col];
            }
        }
    }
    __syncthreads();

    float acc[2][4][4];
#pragma unroll
    for (int mt = 0; mt < 2; mt++)
#pragma unroll
        for (int nt = 0; nt < 4; nt++)
#pragma unroll
            for (int r = 0; r < 4; r++) acc[mt][nt][r] = 0.f;

#pragma unroll
    for (int kk = 0; kk < 64; kk += 16) {
        uint32_t ah[2][4], al[2][4];
#pragma unroll
        for (int mt = 0; mt < 2; mt++) {
            const int r0 = wm + mt * 16 + gid;
            ah[mt][0] = *(const uint32_t*)&sQh[r0 * 72 + kk + tig * 2];
            ah[mt][1] = *(const uint32_t*)&sQh[(r0 + 8) * 72 + kk + tig * 2];
            ah[mt][2] = *(const uint32_t*)&sQh[r0 * 72 + kk + tig * 2 + 8];
            ah[mt][3] = *(const uint32_t*)&sQh[(r0 + 8) * 72 + kk + tig * 2 + 8];
            al[mt][0] = *(const uint32_t*)&sQl[r0 * 72 + kk + tig * 2];
            al[mt][1] = *(const uint32_t*)&sQl[(r0 + 8) * 72 + kk + tig * 2];
            al[mt][2] = *(const uint32_t*)&sQl[r0 * 72 + kk + tig * 2 + 8];
            al[mt][3] = *(const uint32_t*)&sQl[(r0 + 8) * 72 + kk + tig * 2 + 8];
        }
        uint32_t bh2[4][2], bl2[4][2];
#pragma unroll
        for (int nt = 0; nt < 4; nt++) {
            const int c0 = wn + nt * 8 + gid;
            bh2[nt][0] = *(const uint32_t*)&sKh[c0 * 72 + kk + tig * 2];
            bh2[nt][1] = *(const uint32_t*)&sKh[c0 * 72 + kk + tig * 2 + 8];
            bl2[nt][0] = *(const uint32_t*)&sKl[c0 * 72 + kk + tig * 2];
            bl2[nt][1] = *(const uint32_t*)&sKl[c0 * 72 + kk + tig * 2 + 8];
        }
#pragma unroll
        for (int mt = 0; mt < 2; mt++)
#pragma unroll
            for (int nt = 0; nt < 4; nt++)
                MMA_BF16(acc[mt][nt], ah[mt], bh2[nt]);
#pragma unroll
        for (int mt = 0; mt < 2; mt++)
#pragma unroll
            for (int nt = 0; nt < 4; nt++)
                MMA_BF16(acc[mt][nt], ah[mt], bl2[nt]);
#pragma unroll
        for (int mt = 0; mt < 2; mt++)
#pragma unroll
            for (int nt = 0; nt < 4; nt++)
                MMA_BF16(acc[mt][nt], al[mt], bh2[nt]);
    }

#pragma unroll
    for (int mt = 0; mt < 2; mt++)
#pragma unroll
        for (int nt = 0; nt < 4; nt++)
#pragma unroll
            for (int rp = 0; rp < 2; rp++) {
                const int m = bm + wm + mt * 16 + gid + rp * 8;
                const int n = bn + wn + nt * 8 + tig * 2;
                float2 v = make_float2(acc[mt][nt][rp * 2], acc[mt][nt][rp * 2 + 1]);
                *(float2*)&g_s[((size_t)bh * Nn + m) * Nn + n] = v;
            }
}

// ---------------------------------------------------------------------------
// fused talking-heads mix + softmax + mix; writes P2 as bf16 split
// ---------------------------------------------------------------------------
__global__ void __launch_bounds__(576) k_mix_softmax(const float* __restrict__ Wl,
                                                     const float* __restrict__ bl,
                                                     const float* __restrict__ Ww,
                                                     const float* __restrict__ bw) {
    const int bm = blockIdx.x;
    const int b = bm / Nn, m = bm - b * Nn;
    const int n = threadIdx.x;
    const int lane = threadIdx.x & 31, wp = threadIdx.x >> 5;

    __shared__ float sWl[144], sWw[144], sbl[12], sbw[12];
    __shared__ float red[12][20];
    __shared__ float rowstat[12];

    if (threadIdx.x < 144) { sWl[threadIdx.x] = Wl[threadIdx.x]; sWw[threadIdx.x] = Ww[threadIdx.x]; }
    if (threadIdx.x < 12)  { sbl[threadIdx.x] = bl[threadIdx.x]; sbw[threadIdx.x] = bw[threadIdx.x]; }
    __syncthreads();

    const size_t base = ((size_t)(b * Hh) * Nn + m) * Nn + n;
    const size_t hstr = (size_t)Nn * Nn;

    float s[12];
#pragma unroll
    for (int h = 0; h < 12; h++) s[h] = g_s[base + (size_t)h * hstr];

    float a[12];
#pragma unroll
    for (int g = 0; g < 12; g++) {
        float acc = sbl[g];
#pragma unroll
        for (int h = 0; h < 12; h++) acc = fmaf(sWl[g * 12 + h], s[h], acc);
        a[g] = acc;
    }

#pragma unroll
    for (int g = 0; g < 12; g++) {
        float v = a[g];
#pragma unroll
        for (int o = 16; o > 0; o >>= 1) v = fmaxf(v, __shfl_xor_sync(0xffffffffu, v, o));
        if (lane == 0) red[g][wp] = v;
    }
    __syncthreads();
    if (threadIdx.x < 12) {
        float v = red[threadIdx.x][0];
        for (int w2 = 1; w2 < 18; w2++) v = fmaxf(v, red[threadIdx.x][w2]);
        rowstat[threadIdx.x] = v;
    }
    __syncthreads();

    float p[12];
#pragma unroll
    for (int g = 0; g < 12; g++) p[g] = __expf(a[g] - rowstat[g]);
    __syncthreads();

#pragma unroll
    for (int g = 0; g < 12; g++) {
        float v = p[g];
#pragma unroll
        for (int o = 16; o > 0; o >>= 1) v += __shfl_xor_sync(0xffffffffu, v, o);
        if (lane == 0) red[g][wp] = v;
    }
    __syncthreads();
    if (threadIdx.x < 12) {
        float v = 0.f;
        for (int w2 = 0; w2 < 18; w2++) v += red[threadIdx.x][w2];
        rowstat[threadIdx.x] = 1.0f / v;
    }
    __syncthreads();

#pragma unroll
    for (int g = 0; g < 12; g++) p[g] *= rowstat[g];

#pragma unroll
    for (int g = 0; g < 12; g++) {
        float acc = sbw[g];
#pragma unroll
        for (int h = 0; h < 12; h++) acc = fmaf(sWw[g * 12 + h], p[h], acc);
        split_store(g_p2h, g_p2l, base + (size_t)g * hstr, acc);
    }
}

// ---------------------------------------------------------------------------
// PV: per (b,h): O[m,d] = sum_n P2[m,n] Vt[d,n]. CTA 192(m)x64(d), K=576,
// BK=32, 3-stage cp.async, 384 thr. Epilogue writes fp16 split for proj.
// ---------------------------------------------------------------------------
#define PV_SMEM (size_t)((3 * 192 * 40 * 2 + 3 * 64 * 40 * 2) * 2)

__global__ void __launch_bounds__(384, 1) k_pv() {
    extern __shared__ __nv_bfloat16 smpv[];
    __nv_bfloat16* sPh = smpv;                    // 3 stages of [192][40]
    __nv_bfloat16* sPl = sPh + 3 * 192 * 40;
    __nv_bfloat16* sVh = sPl + 3 * 192 * 40;      // 3 stages of [64][40]
    __nv_bfloat16* sVl = sVh + 3 * 64 * 40;

    const int bh = blockIdx.y;
    const int bm = blockIdx.x * 192;
    const int t = threadIdx.x, lane = t & 31, warp = t >> 5;
    const int gid = lane >> 2, tig = lane & 3;
    const int wm = (warp >> 1) * 32, wn = (warp & 1) * 32;

    const int prow = t >> 1, pcol = (t & 1) * 16;
    const __nv_bfloat16* gPh = g_p2h + ((size_t)bh * Nn + bm + prow) * Nn + pcol;
    const __nv_bfloat16* gPl = g_p2l + ((size_t)bh * Nn + bm + prow) * Nn + pcol;
    const int vrow = (t < 128) ? prow : 0;
    const __nv_bfloat16* gVh = g_vth + ((size_t)bh * HDm + vrow) * Nn + pcol;
    const __nv_bfloat16* gVl = g_vtl + ((size_t)bh * HDm + vrow) * Nn + pcol;

    const uint32_t dPh = smem_u32(sPh) + (uint32_t)(prow * 40 + pcol) * 2;
    const uint32_t dPl = smem_u32(sPl) + (uint32_t)(prow * 40 + pcol) * 2;
    const uint32_t dVh = smem_u32(sVh) + (uint32_t)(vrow * 40 + pcol) * 2;
    const uint32_t dVl = smem_u32(sVl) + (uint32_t)(vrow * 40 + pcol) * 2;
    const uint32_t stP = 192 * 40 * 2, stV = 64 * 40 * 2;

    auto issue = [&](int s, int kt) {
        const int k0 = kt * 32;
        cp16(dPh + s * stP,      gPh + k0);
        cp16(dPh + s * stP + 16, gPh + k0 + 8);
        cp16(dPl + s * stP,      gPl + k0);
        cp16(dPl + s * stP + 16, gPl + k0 + 8);
        if (t < 128) {
            cp16(dVh + s * stV,      gVh + k0);
            cp16(dVh + s * stV + 16, gVh + k0 + 8);
            cp16(dVl + s * stV,      gVl + k0);
            cp16(dVl + s * stV + 16, gVl + k0 + 8);
        }
        CP_COMMIT();
    };

    float acc[2][4][4];
#pragma unroll
    for (int mt = 0; mt < 2; mt++)
#pragma unroll
        for (int nt = 0; nt < 4; nt++)
#pragma unroll
            for (int r = 0; r < 4; r++) acc[mt][nt][r] = 0.f;

    const int KT = Nn / 32;   // 18
    issue(0, 0);
    issue(1, 1);

    for (int kt = 0; kt < KT; kt++) {
        const int st = kt % 3;
        if (kt + 1 < KT) { CP_WAIT(1); } else { CP_WAIT(0); }
        __syncthreads();
        if (kt + 2 < KT) issue((kt + 2) % 3, kt + 2);

        const __nv_bfloat16* pPh = sPh + st * 192 * 40;
        const __nv_bfloat16* pPl = sPl + st * 192 * 40;
        const __nv_bfloat16* pVh = sVh + st * 64 * 40;
        const __nv_bfloat16* pVl = sVl + st * 64 * 40;
#pragma unroll
        for (int kk = 0; kk < 32; kk += 16) {
            uint32_t ah[2][4], al[2][4];
#pragma unroll
            for (int mt = 0; mt < 2; mt++) {
                const int r0 = wm + mt * 16 + gid;
                ah[mt][0] = *(const uint32_t*)&pPh[r0 * 40 + kk + tig * 2];
                ah[mt][1] = *(const uint32_t*)&pPh[(r0 + 8) * 40 + kk + tig * 2];
                ah[mt][2] = *(const uint32_t*)&pPh[r0 * 40 + kk + tig * 2 + 8];
                ah[mt][3] = *(const uint32_t*)&pPh[(r0 + 8) * 40 + kk + tig * 2 + 8];
                al[mt][0] = *(const uint32_t*)&pPl[r0 * 40 + kk + tig * 2];
                al[mt][1] = *(const uint32_t*)&pPl[(r0 + 8) * 40 + kk + tig * 2];
                al[mt][2] = *(const uint32_t*)&pPl[r0 * 40 + kk + tig * 2 + 8];
                al[mt][3] = *(const uint32_t*)&pPl[(r0 + 8) * 40 + kk + tig * 2 + 8];
            }
            uint32_t bh2[4][2], bl2[4][2];
#pragma unroll
            for (int nt = 0; nt < 4; nt++) {
                const int c0 = wn + nt * 8 + gid;
                bh2[nt][0] = *(const uint32_t*)&pVh[c0 * 40 + kk + tig * 2];
                bh2[nt][1] = *(const uint32_t*)&pVh[c0 * 40 + kk + tig * 2 + 8];
                bl2[nt][0] = *(const uint32_t*)&pVl[c0 * 40 + kk + tig * 2];
                bl2[nt][1] = *(const uint32_t*)&pVl[c0 * 40 + kk + tig * 2 + 8];
            }
#pragma unroll
            for (int mt = 0; mt < 2; mt++)
#pragma unroll
                for (int nt = 0; nt < 4; nt++)
                    MMA_BF16(acc[mt][nt], ah[mt], bh2[nt]);
#pragma unroll
            for (int mt = 0; mt < 2; mt++)
#pragma unroll
                for (int nt = 0; nt < 4; nt++)
                    MMA_BF16(acc[mt][nt], ah[mt], bl2[nt]);
#pragma unroll
            for (int mt = 0; mt < 2; mt++)
#pragma unroll
                for (int nt = 0; nt < 4; nt++)
                    MMA_BF16(acc[mt][nt], al[mt], bh2[nt]);
        }
    }

    const int b = bh / Hh, h = bh - b * Hh;
#pragma unroll
    for (int mt = 0; mt < 2; mt++)
#pragma unroll
        for (int nt = 0; nt < 4; nt++)
#pragma unroll
            for (int rp = 0; rp < 2; rp++) {
                const int m = bm + wm + mt * 16 + gid + rp * 8;
                const int d = wn + nt * 8 + tig * 2;
                const size_t idx = ((size_t)(b * Nn + m)) * Cc + h * HDm + d;
                const float v0 = acc[mt][nt][rp * 2];
                const float v1 = acc[mt][nt][rp * 2 + 1];
                __half h0 = __float2half_rn(v0);
                __half h1 = __float2half_rn(v1);
                __half2 hp; hp.x = h0; hp.y = h1;
                __half2 lp;
                lp.x = __float2half_rn(v0 - __half2float(h0));
                lp.y = __float2half_rn(v1 - __half2float(h1));
                *(__half2*)&g_ohh[idx] = hp;
                *(__half2*)&g_ohl[idx] = lp;
            }
}

// ---------------------------------------------------------------------------
extern "C" void kernel_launch(void* const* d_in, const int* in_sizes, int n_in,
                              void* d_out, int out_size) {
    const float* x     = (const float*)d_in[0];
    const float* Wqkv  = (const float*)d_in[1];
    const float* Wl    = (const float*)d_in[2];
    const float* bl    = (const float*)d_in[3];
    const float* Ww    = (const float*)d_in[4];
    const float* bw    = (const float*)d_in[5];
    const float* Wproj = (const float*)d_in[6];
    const float* bproj = (const float*)d_in[7];
    float* out = (float*)d_out;

    __half *xh, *xl, *wqh, *wph, *ohh, *ohl;
    cudaGetSymbolAddress((void**)&xh,  g_xh);  cudaGetSymbolAddress((void**)&xl,  g_xl);
    cudaGetSymbolAddress((void**)&wqh, g_wqh);
    cudaGetSymbolAddress((void**)&wph, g_wph);
    cudaGetSymbolAddress((void**)&ohh, g_ohh); cudaGetSymbolAddress((void**)&ohl, g_ohl);

    cudaFuncSetAttribute(k_gemm<0>, cudaFuncAttributeMaxDynamicSharedMemorySize, (int)GEMM_SMEM);
    cudaFuncSetAttribute(k_gemm<1>, cudaFuncAttributeMaxDynamicSharedMemorySize, (int)GEMM_SMEM);
    cudaFuncSetAttribute(k_scores,  cudaFuncAttributeMaxDynamicSharedMemorySize, (int)SC_SMEM);
    cudaFuncSetAttribute(k_pv,      cudaFuncAttributeMaxDynamicSharedMemorySize, (int)PV_SMEM);

    const int nX  = BN * Cc;
    const int nWq = C3 * Cc;
    const int nWp = Cc * Cc;
    k_split_pair_h<<<(nX  + 255) / 256, 256>>>(x,     xh,  xl, nX);
    k_cvt_h<<<(nWq + 255) / 256, 256>>>(Wqkv,  wqh, nWq);
    k_cvt_h<<<(nWp + 255) / 256, 256>>>(Wproj, wph, nWp);

    k_gemm<0><<<dim3(C3 / 64, BN / 128), 256, GEMM_SMEM>>>(xh, xl, wqh, nullptr, nullptr);
    k_scores<<<dim3(Nn / 64, Nn / 192, BH), 384, SC_SMEM>>>();
    k_mix_softmax<<<BN, 576>>>(Wl, bl, Ww, bw);
    k_pv<<<dim3(Nn / 192, BH), 384, PV_SMEM>>>();
    k_gemm<1><<<dim3(Cc / 64, BN / 128), 256, GEMM_SMEM>>>(ohh, ohl, wph, bproj, out);
}